// round 3
// baseline (speedup 1.0000x reference)
#include <cuda_runtime.h>
#include <cuda_bf16.h>
#include <math.h>

// Problem constants (B=1)
#define S_LEN   2048
#define HDIM    4096
#define NHEADS  32
#define NKVH    8
#define DHEAD   128
#define IDIM    11008

// ---------------------------------------------------------------------------
// Pooled scratch (single device global: allocation-free per harness rules)
// Offsets in floats.
// ---------------------------------------------------------------------------
#define OFF_CAT   0                                      // [S, 2H]
#define OFF_X     (OFF_CAT  + S_LEN * 2 * HDIM)          // [S, H]
#define OFF_H     (OFF_X    + S_LEN * HDIM)              // [S, H]
#define OFF_Q     (OFF_H    + S_LEN * HDIM)              // [S, NH*D]
#define OFF_K     (OFF_Q    + S_LEN * NHEADS * DHEAD)    // [S, NKV*D]
#define OFF_V     (OFF_K    + S_LEN * NKVH * DHEAD)
#define OFF_ATTN  (OFF_V    + S_LEN * NKVH * DHEAD)      // [S, NH*D]
#define OFF_X2    (OFF_ATTN + S_LEN * NHEADS * DHEAD)    // [S, H]
#define OFF_H2    (OFF_X2   + S_LEN * HDIM)              // [S, H]
#define OFF_GATE  (OFF_H2   + S_LEN * HDIM)              // [S, I]
#define OFF_UP    (OFF_GATE + S_LEN * IDIM)              // [S, I]
#define POOL_SZ   (OFF_UP   + S_LEN * IDIM)

__device__ float g_pool[POOL_SZ];

// ---------------------------------------------------------------------------
// concat: cat[s, 0:H] = inputs_embeds, cat[s, H:2H] = hidden_states
// ---------------------------------------------------------------------------
__global__ void concat_kernel(const float* __restrict__ emb,
                              const float* __restrict__ hid,
                              float* __restrict__ cat)
{
    int i = blockIdx.x * blockDim.x + threadIdx.x;      // float4 index
    const int total4 = S_LEN * 2 * HDIM / 4;
    if (i >= total4) return;
    int row = i / (2 * HDIM / 4);
    int c4  = i % (2 * HDIM / 4);
    float4 v;
    if (c4 < HDIM / 4) v = ((const float4*)emb)[row * (HDIM / 4) + c4];
    else               v = ((const float4*)hid)[row * (HDIM / 4) + (c4 - HDIM / 4)];
    ((float4*)cat)[i] = v;
}

// ---------------------------------------------------------------------------
// Tiled NT SGEMM: C[M,N] = A[M,K] * B[N,K]^T (+bias[col]) (+resid[M,N])
// 128x128 tile, BK=8, 256 threads, 8x8 per thread. Requires M%128==N%128==K%8==0.
// ---------------------------------------------------------------------------
__global__ __launch_bounds__(256) void sgemm_nt(
    int M, int N, int K,
    const float* __restrict__ A, const float* __restrict__ B,
    const float* __restrict__ bias, const float* __restrict__ resid,
    float* __restrict__ C)
{
    __shared__ float As[8][128];
    __shared__ float Bs[8][128];

    const int tid = threadIdx.x;
    const int tx = tid & 15;
    const int ty = tid >> 4;
    const int bx = blockIdx.x, by = blockIdx.y;

    const float* Ab = A + (size_t)by * 128 * K;
    const float* Bb = B + (size_t)bx * 128 * K;

    const int lr = tid >> 1;          // 0..127 tile row
    const int lc = (tid & 1) * 4;     // 0 or 4 (k offset)

    float acc[8][8];
    #pragma unroll
    for (int i = 0; i < 8; i++)
        #pragma unroll
        for (int j = 0; j < 8; j++) acc[i][j] = 0.f;

    float4 pa = *(const float4*)(Ab + (size_t)lr * K + lc);
    float4 pb = *(const float4*)(Bb + (size_t)lr * K + lc);

    const int nt = K >> 3;
    for (int t = 0; t < nt; ++t) {
        As[lc + 0][lr] = pa.x; As[lc + 1][lr] = pa.y;
        As[lc + 2][lr] = pa.z; As[lc + 3][lr] = pa.w;
        Bs[lc + 0][lr] = pb.x; Bs[lc + 1][lr] = pb.y;
        Bs[lc + 2][lr] = pb.z; Bs[lc + 3][lr] = pb.w;
        __syncthreads();
        if (t + 1 < nt) {
            pa = *(const float4*)(Ab + (size_t)lr * K + (t + 1) * 8 + lc);
            pb = *(const float4*)(Bb + (size_t)lr * K + (t + 1) * 8 + lc);
        }
        #pragma unroll
        for (int kk = 0; kk < 8; ++kk) {
            float4 a0 = *(const float4*)&As[kk][ty * 8];
            float4 a1 = *(const float4*)&As[kk][ty * 8 + 4];
            float4 b0 = *(const float4*)&Bs[kk][tx * 8];
            float4 b1 = *(const float4*)&Bs[kk][tx * 8 + 4];
            float ra[8] = {a0.x, a0.y, a0.z, a0.w, a1.x, a1.y, a1.z, a1.w};
            float rb[8] = {b0.x, b0.y, b0.z, b0.w, b1.x, b1.y, b1.z, b1.w};
            #pragma unroll
            for (int i = 0; i < 8; i++)
                #pragma unroll
                for (int j = 0; j < 8; j++)
                    acc[i][j] += ra[i] * rb[j];
        }
        __syncthreads();
    }

    const int row0 = by * 128 + ty * 8;
    const int col0 = bx * 128 + tx * 8;

    float4 bv0 = make_float4(0.f, 0.f, 0.f, 0.f), bv1 = bv0;
    if (bias) {
        bv0 = *(const float4*)(bias + col0);
        bv1 = *(const float4*)(bias + col0 + 4);
    }

    #pragma unroll
    for (int i = 0; i < 8; i++) {
        float4 o0 = make_float4(acc[i][0] + bv0.x, acc[i][1] + bv0.y,
                                acc[i][2] + bv0.z, acc[i][3] + bv0.w);
        float4 o1 = make_float4(acc[i][4] + bv1.x, acc[i][5] + bv1.y,
                                acc[i][6] + bv1.z, acc[i][7] + bv1.w);
        size_t off = (size_t)(row0 + i) * N + col0;
        if (resid) {
            float4 r0 = *(const float4*)(resid + off);
            float4 r1 = *(const float4*)(resid + off + 4);
            o0.x += r0.x; o0.y += r0.y; o0.z += r0.z; o0.w += r0.w;
            o1.x += r1.x; o1.y += r1.y; o1.z += r1.z; o1.w += r1.w;
        }
        *(float4*)(C + off)     = o0;
        *(float4*)(C + off + 4) = o1;
    }
}

// ---------------------------------------------------------------------------
// RMSNorm over last dim (H=4096), one block per row
// ---------------------------------------------------------------------------
__global__ __launch_bounds__(256) void rmsnorm_kernel(
    const float* __restrict__ x, const float* __restrict__ w,
    float* __restrict__ y)
{
    const int row = blockIdx.x;
    const float4* xr = (const float4*)(x + (size_t)row * HDIM);
    float ss = 0.f;
    for (int i = threadIdx.x; i < HDIM / 4; i += 256) {
        float4 v = xr[i];
        ss += v.x * v.x + v.y * v.y + v.z * v.z + v.w * v.w;
    }
    #pragma unroll
    for (int o = 16; o > 0; o >>= 1) ss += __shfl_xor_sync(0xffffffffu, ss, o);
    __shared__ float red[8];
    __shared__ float s_scale;
    if ((threadIdx.x & 31) == 0) red[threadIdx.x >> 5] = ss;
    __syncthreads();
    if (threadIdx.x == 0) {
        float tot = 0.f;
        #pragma unroll
        for (int i = 0; i < 8; i++) tot += red[i];
        s_scale = rsqrtf(tot / (float)HDIM + 1e-6f);
    }
    __syncthreads();
    const float sc = s_scale;
    const float4* wr = (const float4*)w;
    float4* yr = (float4*)(y + (size_t)row * HDIM);
    for (int i = threadIdx.x; i < HDIM / 4; i += 256) {
        float4 v = xr[i], ww = wr[i];
        yr[i] = make_float4(v.x * sc * ww.x, v.y * sc * ww.y,
                            v.z * sc * ww.z, v.w * sc * ww.w);
    }
}

// ---------------------------------------------------------------------------
// RoPE in place. grid = (S, nheads), 64 threads (one per rotation pair).
// position_ids is definitionally arange(S) (broadcast), so use the row index
// directly -- avoids any dependence on the stored dtype (int32 vs int64).
// Phases in fp64 so cos/sin stay within ~1e-4 of the fp32 reference cache.
// ---------------------------------------------------------------------------
__global__ void rope_kernel(float* __restrict__ t, int rowstride)
{
    const int s = blockIdx.x;
    const int h = blockIdx.y;
    const int d = threadIdx.x;  // 0..63
    float* base = t + (size_t)s * rowstride + h * DHEAD;
    const double p = (double)s;
    // inv_freq = 10000^(-d/64) = exp(-d * ln(10000)/64)
    const double invf = exp(-(double)d * 0.14391156831212787);
    const double ph = p * invf;
    const float c  = (float)cos(ph);
    const float si = (float)sin(ph);
    const float x1 = base[d];
    const float x2 = base[d + 64];
    base[d]      = x1 * c - x2 * si;
    base[d + 64] = x2 * c + x1 * si;
}

// ---------------------------------------------------------------------------
// Flash attention, fp32, causal (attention_mask is all-ones => no pad mask).
// grid = (S/64 q-blocks, NH heads), 256 threads. BM=BN=64, D=128, GQA rep=4.
// ---------------------------------------------------------------------------
#define FA_SMEM_FLOATS (128*68 + 128*68 + 64*128 + 64*65 + 3*64)

__global__ __launch_bounds__(256) void flash_kernel(
    const float* __restrict__ q, const float* __restrict__ k,
    const float* __restrict__ v, float* __restrict__ out)
{
    extern __shared__ float sm[];
    float* Qst  = sm;                 // [128][68]  d-major (transposed), pad 4
    float* Kst  = Qst + 128 * 68;     // [128][68]
    float* Vs   = Kst + 128 * 68;     // [64][128]  row(key)-major
    float* Ps   = Vs + 64 * 128;      // [64][65]
    float* rowm = Ps + 64 * 65;
    float* rowl = rowm + 64;
    float* rowa = rowl + 64;

    const int tid = threadIdx.x;
    const int tx = tid & 15;
    const int ty = tid >> 4;
    const int h  = blockIdx.y;
    const int m0 = blockIdx.x * 64;
    const int kvh = h >> 2;           // n_rep = 4
    const float* qb = q + (size_t)h * DHEAD;
    const float* kb = k + (size_t)kvh * DHEAD;
    const float* vb = v + (size_t)kvh * DHEAD;
    const float scale = 0.08838834764831845f;   // 1/sqrt(128)

    // Load Q tile transposed: Qst[d][r]
    for (int i = tid; i < 64 * 128; i += 256) {
        int r = i >> 7, d = i & 127;
        Qst[d * 68 + r] = qb[(size_t)(m0 + r) * (NHEADS * DHEAD) + d];
    }
    if (tid < 64) { rowm[tid] = -INFINITY; rowl[tid] = 0.f; }

    float accO[4][8];
    #pragma unroll
    for (int i = 0; i < 4; i++)
        #pragma unroll
        for (int j = 0; j < 8; j++) accO[i][j] = 0.f;

    const int ntiles = blockIdx.x + 1;   // causal
    for (int t = 0; t < ntiles; ++t) {
        const int n0 = t * 64;
        __syncthreads();   // prior tile's PV done before overwriting K/V/P
        for (int i = tid; i < 64 * 128; i += 256) {
            int r = i >> 7, d = i & 127;
            Kst[d * 68 + r] = kb[(size_t)(n0 + r) * (NKVH * DHEAD) + d];
        }
        for (int i = tid; i < 64 * 32; i += 256) {
            int r = i >> 5, c = i & 31;
            ((float4*)(Vs + r * 128))[c] =
                ((const float4*)(vb + (size_t)(n0 + r) * (NKVH * DHEAD)))[c];
        }
        __syncthreads();

        // S = Q K^T : each thread a 4x4 micro-tile
        float sacc[4][4];
        #pragma unroll
        for (int i = 0; i < 4; i++)
            #pragma unroll
            for (int j = 0; j < 4; j++) sacc[i][j] = 0.f;

        #pragma unroll 8
        for (int kk = 0; kk < 128; ++kk) {
            float4 a = *(const float4*)(Qst + kk * 68 + ty * 4);
            float4 b = *(const float4*)(Kst + kk * 68 + tx * 4);
            float ra[4] = {a.x, a.y, a.z, a.w};
            float rb[4] = {b.x, b.y, b.z, b.w};
            #pragma unroll
            for (int i = 0; i < 4; i++)
                #pragma unroll
                for (int j = 0; j < 4; j++)
                    sacc[i][j] += ra[i] * rb[j];
        }

        // scale + causal mask, write to Ps
        #pragma unroll
        for (int i = 0; i < 4; i++) {
            const int gq = m0 + ty * 4 + i;
            #pragma unroll
            for (int j = 0; j < 4; j++) {
                const int gk = n0 + tx * 4 + j;
                float sv = sacc[i][j] * scale;
                if (gk > gq) sv = -1e30f;
                Ps[(ty * 4 + i) * 65 + tx * 4 + j] = sv;
            }
        }
        __syncthreads();

        // online softmax: one thread per row
        if (tid < 64) {
            float* pr = Ps + tid * 65;
            float mloc = -INFINITY;
            #pragma unroll 8
            for (int c = 0; c < 64; ++c) mloc = fmaxf(mloc, pr[c]);
            const float mold = rowm[tid];
            const float mnew = fmaxf(mold, mloc);
            const float alpha = (mold == -INFINITY) ? 0.f : expf(mold - mnew);
            float lsum = 0.f;
            #pragma unroll 8
            for (int c = 0; c < 64; ++c) {
                float pv = expf(pr[c] - mnew);
                pr[c] = pv;
                lsum += pv;
            }
            rowl[tid] = rowl[tid] * alpha + lsum;
            rowm[tid] = mnew;
            rowa[tid] = alpha;
        }
        __syncthreads();

        // O = O*alpha + P V
        float al[4];
        #pragma unroll
        for (int i = 0; i < 4; i++) al[i] = rowa[ty * 4 + i];
        #pragma unroll
        for (int i = 0; i < 4; i++)
            #pragma unroll
            for (int j = 0; j < 8; j++) accO[i][j] *= al[i];

        #pragma unroll 4
        for (int kk = 0; kk < 64; ++kk) {
            float4 v0 = *(const float4*)(Vs + kk * 128 + tx * 8);
            float4 v1 = *(const float4*)(Vs + kk * 128 + tx * 8 + 4);
            #pragma unroll
            for (int i = 0; i < 4; i++) {
                const float pv = Ps[(ty * 4 + i) * 65 + kk];
                accO[i][0] += pv * v0.x; accO[i][1] += pv * v0.y;
                accO[i][2] += pv * v0.z; accO[i][3] += pv * v0.w;
                accO[i][4] += pv * v1.x; accO[i][5] += pv * v1.y;
                accO[i][6] += pv * v1.z; accO[i][7] += pv * v1.w;
            }
        }
    }

    // normalize + write [S, NH*D]
    #pragma unroll
    for (int i = 0; i < 4; i++) {
        const int r = ty * 4 + i;
        const float invl = 1.f / rowl[r];
        float4 o0 = make_float4(accO[i][0] * invl, accO[i][1] * invl,
                                accO[i][2] * invl, accO[i][3] * invl);
        float4 o1 = make_float4(accO[i][4] * invl, accO[i][5] * invl,
                                accO[i][6] * invl, accO[i][7] * invl);
        float* ob = out + (size_t)(m0 + r) * (NHEADS * DHEAD) + h * DHEAD + tx * 8;
        *(float4*)(ob)     = o0;
        *(float4*)(ob + 4) = o1;
    }
}

// ---------------------------------------------------------------------------
// silu(gate) * up  (float4 elementwise)
// ---------------------------------------------------------------------------
__global__ void silu_mul_kernel(const float* __restrict__ g,
                                const float* __restrict__ u,
                                float* __restrict__ o, int n4)
{
    int i = blockIdx.x * blockDim.x + threadIdx.x;
    if (i >= n4) return;
    float4 gg = ((const float4*)g)[i];
    float4 uu = ((const float4*)u)[i];
    float4 r;
    r.x = gg.x / (1.f + expf(-gg.x)) * uu.x;
    r.y = gg.y / (1.f + expf(-gg.y)) * uu.y;
    r.z = gg.z / (1.f + expf(-gg.z)) * uu.z;
    r.w = gg.w / (1.f + expf(-gg.w)) * uu.w;
    ((float4*)o)[i] = r;
}

// ---------------------------------------------------------------------------
// Host orchestration
// ---------------------------------------------------------------------------
extern "C" void kernel_launch(void* const* d_in, const int* in_sizes, int n_in,
                              void* d_out, int out_size)
{
    const float* hidden      = (const float*)d_in[0];
    const float* embeds      = (const float*)d_in[1];
    // d_in[2] attention_mask: all ones in this problem -> pad mask is zero
    const float* fc_w        = (const float*)d_in[3];
    const float* fc_b        = (const float*)d_in[4];
    const float* in_norm_w   = (const float*)d_in[5];
    const float* q_w         = (const float*)d_in[6];
    const float* k_w         = (const float*)d_in[7];
    const float* v_w         = (const float*)d_in[8];
    const float* o_w         = (const float*)d_in[9];
    const float* post_norm_w = (const float*)d_in[10];
    const float* gate_w      = (const float*)d_in[11];
    const float* up_w        = (const float*)d_in[12];
    const float* down_w      = (const float*)d_in[13];
    // d_in[14] position_ids == arange(S): handled implicitly in rope_kernel

    float* pool = nullptr;
    cudaGetSymbolAddress((void**)&pool, g_pool);
    float* cat  = pool + OFF_CAT;
    float* x    = pool + OFF_X;
    float* h    = pool + OFF_H;
    float* q    = pool + OFF_Q;
    float* k    = pool + OFF_K;
    float* v    = pool + OFF_V;
    float* attn = pool + OFF_ATTN;
    float* x2   = pool + OFF_X2;
    float* h2   = pool + OFF_H2;
    float* gate = pool + OFF_GATE;
    float* up   = pool + OFF_UP;

    const int fa_smem = FA_SMEM_FLOATS * (int)sizeof(float);
    cudaFuncSetAttribute(flash_kernel,
                         cudaFuncAttributeMaxDynamicSharedMemorySize, fa_smem);

    // 1. concat
    {
        const int n4 = S_LEN * 2 * HDIM / 4;
        concat_kernel<<<(n4 + 255) / 256, 256>>>(embeds, hidden, cat);
    }
    // 2. fc: x = cat @ fc_w^T + fc_b
    sgemm_nt<<<dim3(HDIM / 128, S_LEN / 128), 256>>>(
        S_LEN, HDIM, 2 * HDIM, cat, fc_w, fc_b, nullptr, x);
    // 3. rmsnorm 1
    rmsnorm_kernel<<<S_LEN, 256>>>(x, in_norm_w, h);
    // 4. Q/K/V projections
    sgemm_nt<<<dim3((NHEADS * DHEAD) / 128, S_LEN / 128), 256>>>(
        S_LEN, NHEADS * DHEAD, HDIM, h, q_w, nullptr, nullptr, q);
    sgemm_nt<<<dim3((NKVH * DHEAD) / 128, S_LEN / 128), 256>>>(
        S_LEN, NKVH * DHEAD, HDIM, h, k_w, nullptr, nullptr, k);
    sgemm_nt<<<dim3((NKVH * DHEAD) / 128, S_LEN / 128), 256>>>(
        S_LEN, NKVH * DHEAD, HDIM, h, v_w, nullptr, nullptr, v);
    // 5. RoPE in place (position == row index)
    rope_kernel<<<dim3(S_LEN, NHEADS), 64>>>(q, NHEADS * DHEAD);
    rope_kernel<<<dim3(S_LEN, NKVH),  64>>>(k, NKVH * DHEAD);
    // 6. flash attention
    flash_kernel<<<dim3(S_LEN / 64, NHEADS), 256, fa_smem>>>(q, k, v, attn);
    // 7. O projection + residual: x2 = x + attn @ o_w^T
    sgemm_nt<<<dim3(HDIM / 128, S_LEN / 128), 256>>>(
        S_LEN, HDIM, NHEADS * DHEAD, attn, o_w, nullptr, x, x2);
    // 8. rmsnorm 2
    rmsnorm_kernel<<<S_LEN, 256>>>(x2, post_norm_w, h2);
    // 9. gate / up
    sgemm_nt<<<dim3(IDIM / 128, S_LEN / 128), 256>>>(
        S_LEN, IDIM, HDIM, h2, gate_w, nullptr, nullptr, gate);
    sgemm_nt<<<dim3(IDIM / 128, S_LEN / 128), 256>>>(
        S_LEN, IDIM, HDIM, h2, up_w, nullptr, nullptr, up);
    // 10. silu(gate)*up (in place into gate)
    {
        const int n4 = S_LEN * IDIM / 4;
        silu_mul_kernel<<<(n4 + 255) / 256, 256>>>(gate, up, gate, n4);
    }
    // 11. down + residual -> d_out
    sgemm_nt<<<dim3(HDIM / 128, S_LEN / 128), 256>>>(
        S_LEN, HDIM, IDIM, gate, down_w, nullptr, x2, (float*)d_out);
}

// round 4
// speedup vs baseline: 1.8675x; 1.8675x over previous
#include <cuda_runtime.h>
#include <cuda_bf16.h>
#include <math.h>
#include <stdint.h>

// Problem constants (B=1)
#define S_LEN   2048
#define HDIM    4096
#define NHEADS  32
#define NKVH    8
#define DHEAD   128
#define IDIM    11008

// ---------------------------------------------------------------------------
// fp32 scratch pool
// ---------------------------------------------------------------------------
#define OFF_CAT   0                                      // [S, 2H]
#define OFF_X     (OFF_CAT  + S_LEN * 2 * HDIM)          // [S, H]
#define OFF_H     (OFF_X    + S_LEN * HDIM)              // [S, H]
#define OFF_Q     (OFF_H    + S_LEN * HDIM)              // [S, NH*D]
#define OFF_K     (OFF_Q    + S_LEN * NHEADS * DHEAD)
#define OFF_V     (OFF_K    + S_LEN * NKVH * DHEAD)
#define OFF_ATTN  (OFF_V    + S_LEN * NKVH * DHEAD)
#define OFF_X2    (OFF_ATTN + S_LEN * NHEADS * DHEAD)
#define OFF_H2    (OFF_X2   + S_LEN * HDIM)
#define OFF_GATE  (OFF_H2   + S_LEN * HDIM)              // [S, I]
#define OFF_UP    (OFF_GATE + S_LEN * IDIM)              // [S, I]
#define POOL_SZ   (OFF_UP   + S_LEN * IDIM)

__device__ float g_pool[POOL_SZ];

// ---------------------------------------------------------------------------
// bf16 split pool: for each array, [hi(size) | lo(size)]
// ---------------------------------------------------------------------------
#define BE_CAT   (S_LEN * 2 * HDIM)
#define BE_H     (S_LEN * HDIM)
#define BE_ATTN  (S_LEN * NHEADS * DHEAD)
#define BE_ACT   (S_LEN * IDIM)
#define BE_FCW   (HDIM * 2 * HDIM)
#define BE_QW    (NHEADS * DHEAD * HDIM)
#define BE_KW    (NKVH * DHEAD * HDIM)
#define BE_OW    (HDIM * NHEADS * DHEAD)
#define BE_GW    (IDIM * HDIM)
#define BE_DW    (HDIM * IDIM)

#define BO_CAT   0
#define BO_H     (BO_CAT  + 2 * BE_CAT)
#define BO_ATTN  (BO_H    + 2 * BE_H)
#define BO_H2    (BO_ATTN + 2 * BE_ATTN)
#define BO_ACT   (BO_H2   + 2 * BE_H)
#define BO_FCW   (BO_ACT  + 2 * BE_ACT)
#define BO_QW    (BO_FCW  + 2 * BE_FCW)
#define BO_KW    (BO_QW   + 2 * BE_QW)
#define BO_VW    (BO_KW   + 2 * BE_KW)
#define BO_OW    (BO_VW   + 2 * BE_KW)
#define BO_GW    (BO_OW   + 2 * BE_OW)
#define BO_UW    (BO_GW   + 2 * BE_GW)
#define BO_DW    (BO_UW   + 2 * BE_GW)
#define BPOOL_SZ (BO_DW   + 2 * BE_DW)

__device__ __nv_bfloat16 g_bpool[BPOOL_SZ];

// ---------------------------------------------------------------------------
// split: hi = bf16(x), lo = bf16(x - hi)
// ---------------------------------------------------------------------------
__global__ void split_kernel(const float* __restrict__ x,
                             __nv_bfloat16* __restrict__ hi,
                             __nv_bfloat16* __restrict__ lo, int n4)
{
    int i = blockIdx.x * blockDim.x + threadIdx.x;
    if (i >= n4) return;
    float4 v = ((const float4*)x)[i];
    __nv_bfloat162 h0, h1, l0, l1;
    h0.x = __float2bfloat16_rn(v.x);
    h0.y = __float2bfloat16_rn(v.y);
    h1.x = __float2bfloat16_rn(v.z);
    h1.y = __float2bfloat16_rn(v.w);
    l0.x = __float2bfloat16_rn(v.x - __bfloat162float(h0.x));
    l0.y = __float2bfloat16_rn(v.y - __bfloat162float(h0.y));
    l1.x = __float2bfloat16_rn(v.z - __bfloat162float(h1.x));
    l1.y = __float2bfloat16_rn(v.w - __bfloat162float(h1.y));
    ((__nv_bfloat162*)hi)[2 * i]     = h0;
    ((__nv_bfloat162*)hi)[2 * i + 1] = h1;
    ((__nv_bfloat162*)lo)[2 * i]     = l0;
    ((__nv_bfloat162*)lo)[2 * i + 1] = l1;
}

// ---------------------------------------------------------------------------
// concat
// ---------------------------------------------------------------------------
__global__ void concat_kernel(const float* __restrict__ emb,
                              const float* __restrict__ hid,
                              float* __restrict__ cat)
{
    int i = blockIdx.x * blockDim.x + threadIdx.x;
    const int total4 = S_LEN * 2 * HDIM / 4;
    if (i >= total4) return;
    int row = i / (2 * HDIM / 4);
    int c4  = i % (2 * HDIM / 4);
    float4 v;
    if (c4 < HDIM / 4) v = ((const float4*)emb)[row * (HDIM / 4) + c4];
    else               v = ((const float4*)hid)[row * (HDIM / 4) + (c4 - HDIM / 4)];
    ((float4*)cat)[i] = v;
}

// ---------------------------------------------------------------------------
// Split-bf16 tensor-core NT GEMM:
//   C[M,N] = Ahi*Bhi^T + Ahi*Blo^T + Alo*Bhi^T (+bias)(+resid)
// CTA tile 128x128, BK=32 bf16, 256 threads (8 warps, each 64x32),
// cp.async double-buffered smem. smem row = 40 bf16 (20 words) => fragment
// LDS.32 of (20*r + c) mod 32 is bank-conflict-free.
// Requires M%128==N%128==K%32==0.
// ---------------------------------------------------------------------------
#define GSTRIDE  20                 // words per smem row
#define TILE_W   (128 * GSTRIDE)    // 2560 words per tile
#define STAGE_W  (4 * TILE_W)       // Ahi | Alo | Bhi | Blo
#define GEMM_SMEM_BYTES (2 * STAGE_W * 4)   // 81920

#define MMA_BF16(ac, a0, a1, a2, a3, b0, b1)                                \
    asm volatile(                                                           \
        "mma.sync.aligned.m16n8k16.row.col.f32.bf16.bf16.f32 "              \
        "{%0,%1,%2,%3}, {%4,%5,%6,%7}, {%8,%9}, {%0,%1,%2,%3};"             \
        : "+f"((ac)[0]), "+f"((ac)[1]), "+f"((ac)[2]), "+f"((ac)[3])        \
        : "r"(a0), "r"(a1), "r"(a2), "r"(a3), "r"(b0), "r"(b1))

__global__ __launch_bounds__(256) void gemm_bf16split(
    int M, int N, int K,
    const __nv_bfloat16* __restrict__ Ahi, const __nv_bfloat16* __restrict__ Alo,
    const __nv_bfloat16* __restrict__ Bhi, const __nv_bfloat16* __restrict__ Blo,
    const float* __restrict__ bias, const float* __restrict__ resid,
    float* __restrict__ C)
{
    extern __shared__ uint32_t sw[];

    const int tid  = threadIdx.x;
    const int bx   = blockIdx.x, by = blockIdx.y;
    const int warp = tid >> 5, lane = tid & 31;
    const int wm = warp >> 2, wn = warp & 3;     // warp grid 2(M) x 4(N)
    const int r  = lane >> 2, c = lane & 3;

    // global->smem mapping: thread handles 32B (2x16B) per tile
    const int gr = tid >> 1;         // row 0..127
    const int gc = tid & 1;          // chunk pair

    const size_t arow = (size_t)(by * 128 + gr) * K;
    const size_t brow = (size_t)(bx * 128 + gr) * K;
    const __nv_bfloat16* gsrc[4] = { Ahi + arow, Alo + arow, Bhi + brow, Blo + brow };

    const uint32_t smem_base = (uint32_t)__cvta_generic_to_shared(sw);
    // per-thread smem store word offset within a tile
    const int st_w = gr * GSTRIDE + gc * 8;

    float acc[4][4][4];
    #pragma unroll
    for (int i = 0; i < 4; i++)
        #pragma unroll
        for (int j = 0; j < 4; j++)
            #pragma unroll
            for (int q = 0; q < 4; q++) acc[i][j][q] = 0.f;

    const int nst = K / 32;

    // prologue: stage 0 -> buffer 0
    #pragma unroll
    for (int t = 0; t < 4; t++) {
        const __nv_bfloat16* src = gsrc[t] + gc * 16;
        uint32_t dst = smem_base + (uint32_t)(t * TILE_W + st_w) * 4u;
        asm volatile("cp.async.cg.shared.global [%0], [%1], 16;\n" :: "r"(dst), "l"(src));
        asm volatile("cp.async.cg.shared.global [%0], [%1], 16;\n" :: "r"(dst + 16), "l"(src + 8));
    }
    asm volatile("cp.async.commit_group;\n");
    asm volatile("cp.async.wait_group 0;\n");
    __syncthreads();

    for (int s = 0; s < nst; s++) {
        const int cur = s & 1;
        if (s + 1 < nst) {
            const int nxt = cur ^ 1;
            #pragma unroll
            for (int t = 0; t < 4; t++) {
                const __nv_bfloat16* src = gsrc[t] + (s + 1) * 32 + gc * 16;
                uint32_t dst = smem_base + (uint32_t)(nxt * STAGE_W + t * TILE_W + st_w) * 4u;
                asm volatile("cp.async.cg.shared.global [%0], [%1], 16;\n" :: "r"(dst), "l"(src));
                asm volatile("cp.async.cg.shared.global [%0], [%1], 16;\n" :: "r"(dst + 16), "l"(src + 8));
            }
            asm volatile("cp.async.commit_group;\n");
        }

        const uint32_t* Ah = sw + cur * STAGE_W;
        const uint32_t* Al = Ah + TILE_W;
        const uint32_t* Bh = Ah + 2 * TILE_W;
        const uint32_t* Bl = Ah + 3 * TILE_W;

        #pragma unroll
        for (int k0 = 0; k0 < 2; k0++) {          // two k16 steps; word offset 8*k0
            const int kw = k0 * 8;
            uint32_t ah[4][4], al[4][4];
            #pragma unroll
            for (int i = 0; i < 4; i++) {
                const int m  = wm * 64 + i * 16 + r;
                const int o1 = m * GSTRIDE + kw + c;
                const int o2 = (m + 8) * GSTRIDE + kw + c;
                ah[i][0] = Ah[o1];     ah[i][1] = Ah[o2];
                ah[i][2] = Ah[o1 + 4]; ah[i][3] = Ah[o2 + 4];
                al[i][0] = Al[o1];     al[i][1] = Al[o2];
                al[i][2] = Al[o1 + 4]; al[i][3] = Al[o2 + 4];
            }
            #pragma unroll
            for (int j = 0; j < 4; j++) {
                const int n  = wn * 32 + j * 8 + r;
                const int ob = n * GSTRIDE + kw + c;
                const uint32_t bh0 = Bh[ob], bh1 = Bh[ob + 4];
                const uint32_t bl0 = Bl[ob], bl1 = Bl[ob + 4];
                #pragma unroll
                for (int i = 0; i < 4; i++) {
                    MMA_BF16(acc[i][j], ah[i][0], ah[i][1], ah[i][2], ah[i][3], bh0, bh1);
                    MMA_BF16(acc[i][j], ah[i][0], ah[i][1], ah[i][2], ah[i][3], bl0, bl1);
                    MMA_BF16(acc[i][j], al[i][0], al[i][1], al[i][2], al[i][3], bh0, bh1);
                }
            }
        }

        if (s + 1 < nst) asm volatile("cp.async.wait_group 0;\n");
        __syncthreads();
    }

    // epilogue
    #pragma unroll
    for (int j = 0; j < 4; j++) {
        const int col = bx * 128 + wn * 32 + j * 8 + 2 * c;
        float2 bv = make_float2(0.f, 0.f);
        if (bias) bv = *(const float2*)(bias + col);
        #pragma unroll
        for (int i = 0; i < 4; i++) {
            const int m1 = by * 128 + wm * 64 + i * 16 + r;
            const int m2 = m1 + 8;
            float2 o0 = make_float2(acc[i][j][0] + bv.x, acc[i][j][1] + bv.y);
            float2 o1 = make_float2(acc[i][j][2] + bv.x, acc[i][j][3] + bv.y);
            size_t p0 = (size_t)m1 * N + col;
            size_t p1 = (size_t)m2 * N + col;
            if (resid) {
                float2 r0 = *(const float2*)(resid + p0);
                float2 r1 = *(const float2*)(resid + p1);
                o0.x += r0.x; o0.y += r0.y;
                o1.x += r1.x; o1.y += r1.y;
            }
            *(float2*)(C + p0) = o0;
            *(float2*)(C + p1) = o1;
        }
    }
}

// ---------------------------------------------------------------------------
// RMSNorm over last dim (H=4096), one block per row
// ---------------------------------------------------------------------------
__global__ __launch_bounds__(256) void rmsnorm_kernel(
    const float* __restrict__ x, const float* __restrict__ w,
    float* __restrict__ y)
{
    const int row = blockIdx.x;
    const float4* xr = (const float4*)(x + (size_t)row * HDIM);
    float ss = 0.f;
    for (int i = threadIdx.x; i < HDIM / 4; i += 256) {
        float4 v = xr[i];
        ss += v.x * v.x + v.y * v.y + v.z * v.z + v.w * v.w;
    }
    #pragma unroll
    for (int o = 16; o > 0; o >>= 1) ss += __shfl_xor_sync(0xffffffffu, ss, o);
    __shared__ float red[8];
    __shared__ float s_scale;
    if ((threadIdx.x & 31) == 0) red[threadIdx.x >> 5] = ss;
    __syncthreads();
    if (threadIdx.x == 0) {
        float tot = 0.f;
        #pragma unroll
        for (int i = 0; i < 8; i++) tot += red[i];
        s_scale = rsqrtf(tot / (float)HDIM + 1e-6f);
    }
    __syncthreads();
    const float sc = s_scale;
    const float4* wr = (const float4*)w;
    float4* yr = (float4*)(y + (size_t)row * HDIM);
    for (int i = threadIdx.x; i < HDIM / 4; i += 256) {
        float4 v = xr[i], ww = wr[i];
        yr[i] = make_float4(v.x * sc * ww.x, v.y * sc * ww.y,
                            v.z * sc * ww.z, v.w * sc * ww.w);
    }
}

// ---------------------------------------------------------------------------
// RoPE in place (position == row index; position_ids is arange(S))
// ---------------------------------------------------------------------------
__global__ void rope_kernel(float* __restrict__ t, int rowstride)
{
    const int s = blockIdx.x;
    const int h = blockIdx.y;
    const int d = threadIdx.x;  // 0..63
    float* base = t + (size_t)s * rowstride + h * DHEAD;
    const double p = (double)s;
    const double invf = exp(-(double)d * 0.14391156831212787);
    const double ph = p * invf;
    const float cc = (float)cos(ph);
    const float si = (float)sin(ph);
    const float x1 = base[d];
    const float x2 = base[d + 64];
    base[d]      = x1 * cc - x2 * si;
    base[d + 64] = x2 * cc + x1 * si;
}

// ---------------------------------------------------------------------------
// Flash attention, fp32, causal
// ---------------------------------------------------------------------------
#define FA_SMEM_FLOATS (128*68 + 128*68 + 64*128 + 64*65 + 3*64)

__global__ __launch_bounds__(256) void flash_kernel(
    const float* __restrict__ q, const float* __restrict__ k,
    const float* __restrict__ v, float* __restrict__ out)
{
    extern __shared__ float sm[];
    float* Qst  = sm;
    float* Kst  = Qst + 128 * 68;
    float* Vs   = Kst + 128 * 68;
    float* Ps   = Vs + 64 * 128;
    float* rowm = Ps + 64 * 65;
    float* rowl = rowm + 64;
    float* rowa = rowl + 64;

    const int tid = threadIdx.x;
    const int tx = tid & 15;
    const int ty = tid >> 4;
    const int h  = blockIdx.y;
    const int m0 = blockIdx.x * 64;
    const int kvh = h >> 2;
    const float* qb = q + (size_t)h * DHEAD;
    const float* kb = k + (size_t)kvh * DHEAD;
    const float* vb = v + (size_t)kvh * DHEAD;
    const float scale = 0.08838834764831845f;

    for (int i = tid; i < 64 * 128; i += 256) {
        int r = i >> 7, d = i & 127;
        Qst[d * 68 + r] = qb[(size_t)(m0 + r) * (NHEADS * DHEAD) + d];
    }
    if (tid < 64) { rowm[tid] = -INFINITY; rowl[tid] = 0.f; }

    float accO[4][8];
    #pragma unroll
    for (int i = 0; i < 4; i++)
        #pragma unroll
        for (int j = 0; j < 8; j++) accO[i][j] = 0.f;

    const int ntiles = blockIdx.x + 1;
    for (int t = 0; t < ntiles; ++t) {
        const int n0 = t * 64;
        __syncthreads();
        for (int i = tid; i < 64 * 128; i += 256) {
            int r = i >> 7, d = i & 127;
            Kst[d * 68 + r] = kb[(size_t)(n0 + r) * (NKVH * DHEAD) + d];
        }
        for (int i = tid; i < 64 * 32; i += 256) {
            int r = i >> 5, c = i & 31;
            ((float4*)(Vs + r * 128))[c] =
                ((const float4*)(vb + (size_t)(n0 + r) * (NKVH * DHEAD)))[c];
        }
        __syncthreads();

        float sacc[4][4];
        #pragma unroll
        for (int i = 0; i < 4; i++)
            #pragma unroll
            for (int j = 0; j < 4; j++) sacc[i][j] = 0.f;

        #pragma unroll 8
        for (int kk = 0; kk < 128; ++kk) {
            float4 a = *(const float4*)(Qst + kk * 68 + ty * 4);
            float4 b = *(const float4*)(Kst + kk * 68 + tx * 4);
            float ra[4] = {a.x, a.y, a.z, a.w};
            float rb[4] = {b.x, b.y, b.z, b.w};
            #pragma unroll
            for (int i = 0; i < 4; i++)
                #pragma unroll
                for (int j = 0; j < 4; j++)
                    sacc[i][j] += ra[i] * rb[j];
        }

        #pragma unroll
        for (int i = 0; i < 4; i++) {
            const int gq = m0 + ty * 4 + i;
            #pragma unroll
            for (int j = 0; j < 4; j++) {
                const int gk = n0 + tx * 4 + j;
                float sv = sacc[i][j] * scale;
                if (gk > gq) sv = -1e30f;
                Ps[(ty * 4 + i) * 65 + tx * 4 + j] = sv;
            }
        }
        __syncthreads();

        if (tid < 64) {
            float* pr = Ps + tid * 65;
            float mloc = -INFINITY;
            #pragma unroll 8
            for (int cc = 0; cc < 64; ++cc) mloc = fmaxf(mloc, pr[cc]);
            const float mold = rowm[tid];
            const float mnew = fmaxf(mold, mloc);
            const float alpha = (mold == -INFINITY) ? 0.f : expf(mold - mnew);
            float lsum = 0.f;
            #pragma unroll 8
            for (int cc = 0; cc < 64; ++cc) {
                float pv = expf(pr[cc] - mnew);
                pr[cc] = pv;
                lsum += pv;
            }
            rowl[tid] = rowl[tid] * alpha + lsum;
            rowm[tid] = mnew;
            rowa[tid] = alpha;
        }
        __syncthreads();

        float al[4];
        #pragma unroll
        for (int i = 0; i < 4; i++) al[i] = rowa[ty * 4 + i];
        #pragma unroll
        for (int i = 0; i < 4; i++)
            #pragma unroll
            for (int j = 0; j < 8; j++) accO[i][j] *= al[i];

        #pragma unroll 4
        for (int kk = 0; kk < 64; ++kk) {
            float4 v0 = *(const float4*)(Vs + kk * 128 + tx * 8);
            float4 v1 = *(const float4*)(Vs + kk * 128 + tx * 8 + 4);
            #pragma unroll
            for (int i = 0; i < 4; i++) {
                const float pv = Ps[(ty * 4 + i) * 65 + kk];
                accO[i][0] += pv * v0.x; accO[i][1] += pv * v0.y;
                accO[i][2] += pv * v0.z; accO[i][3] += pv * v0.w;
                accO[i][4] += pv * v1.x; accO[i][5] += pv * v1.y;
                accO[i][6] += pv * v1.z; accO[i][7] += pv * v1.w;
            }
        }
    }

    #pragma unroll
    for (int i = 0; i < 4; i++) {
        const int r = ty * 4 + i;
        const float invl = 1.f / rowl[r];
        float4 o0 = make_float4(accO[i][0] * invl, accO[i][1] * invl,
                                accO[i][2] * invl, accO[i][3] * invl);
        float4 o1 = make_float4(accO[i][4] * invl, accO[i][5] * invl,
                                accO[i][6] * invl, accO[i][7] * invl);
        float* ob = out + (size_t)(m0 + r) * (NHEADS * DHEAD) + h * DHEAD + tx * 8;
        *(float4*)(ob)     = o0;
        *(float4*)(ob + 4) = o1;
    }
}

// ---------------------------------------------------------------------------
// silu(gate) * up
// ---------------------------------------------------------------------------
__global__ void silu_mul_kernel(const float* __restrict__ g,
                                const float* __restrict__ u,
                                float* __restrict__ o, int n4)
{
    int i = blockIdx.x * blockDim.x + threadIdx.x;
    if (i >= n4) return;
    float4 gg = ((const float4*)g)[i];
    float4 uu = ((const float4*)u)[i];
    float4 r;
    r.x = gg.x / (1.f + expf(-gg.x)) * uu.x;
    r.y = gg.y / (1.f + expf(-gg.y)) * uu.y;
    r.z = gg.z / (1.f + expf(-gg.z)) * uu.z;
    r.w = gg.w / (1.f + expf(-gg.w)) * uu.w;
    ((float4*)o)[i] = r;
}

// ---------------------------------------------------------------------------
// Host orchestration
// ---------------------------------------------------------------------------
static inline void split_arr(const float* x, __nv_bfloat16* base, int n)
{
    split_kernel<<<(n / 4 + 255) / 256, 256>>>(x, base, base + n, n / 4);
}

static inline void gemm3(int M, int N, int K,
                         const __nv_bfloat16* Ab, int Aelems,
                         const __nv_bfloat16* Bb, int Belems,
                         const float* bias, const float* resid, float* C)
{
    gemm_bf16split<<<dim3(N / 128, M / 128), 256, GEMM_SMEM_BYTES>>>(
        M, N, K, Ab, Ab + Aelems, Bb, Bb + Belems, bias, resid, C);
}

extern "C" void kernel_launch(void* const* d_in, const int* in_sizes, int n_in,
                              void* d_out, int out_size)
{
    const float* hidden      = (const float*)d_in[0];
    const float* embeds      = (const float*)d_in[1];
    // d_in[2] attention_mask: all ones -> pad mask zero
    const float* fc_w        = (const float*)d_in[3];
    const float* fc_b        = (const float*)d_in[4];
    const float* in_norm_w   = (const float*)d_in[5];
    const float* q_w         = (const float*)d_in[6];
    const float* k_w         = (const float*)d_in[7];
    const float* v_w         = (const float*)d_in[8];
    const float* o_w         = (const float*)d_in[9];
    const float* post_norm_w = (const float*)d_in[10];
    const float* gate_w      = (const float*)d_in[11];
    const float* up_w        = (const float*)d_in[12];
    const float* down_w      = (const float*)d_in[13];
    // d_in[14] position_ids == arange(S)

    float* pool = nullptr;
    cudaGetSymbolAddress((void**)&pool, g_pool);
    float* cat  = pool + OFF_CAT;
    float* x    = pool + OFF_X;
    float* h    = pool + OFF_H;
    float* q    = pool + OFF_Q;
    float* k    = pool + OFF_K;
    float* v    = pool + OFF_V;
    float* attn = pool + OFF_ATTN;
    float* x2   = pool + OFF_X2;
    float* h2   = pool + OFF_H2;
    float* gate = pool + OFF_GATE;
    float* up   = pool + OFF_UP;

    __nv_bfloat16* bp = nullptr;
    cudaGetSymbolAddress((void**)&bp, g_bpool);

    const int fa_smem = FA_SMEM_FLOATS * (int)sizeof(float);
    cudaFuncSetAttribute(flash_kernel,
                         cudaFuncAttributeMaxDynamicSharedMemorySize, fa_smem);
    cudaFuncSetAttribute(gemm_bf16split,
                         cudaFuncAttributeMaxDynamicSharedMemorySize, GEMM_SMEM_BYTES);

    // weight splits (independent of activations)
    split_arr(fc_w,   bp + BO_FCW, BE_FCW);
    split_arr(q_w,    bp + BO_QW,  BE_QW);
    split_arr(k_w,    bp + BO_KW,  BE_KW);
    split_arr(v_w,    bp + BO_VW,  BE_KW);
    split_arr(o_w,    bp + BO_OW,  BE_OW);
    split_arr(gate_w, bp + BO_GW,  BE_GW);
    split_arr(up_w,   bp + BO_UW,  BE_GW);
    split_arr(down_w, bp + BO_DW,  BE_DW);

    // 1. concat + split
    {
        const int n4 = S_LEN * 2 * HDIM / 4;
        concat_kernel<<<(n4 + 255) / 256, 256>>>(embeds, hidden, cat);
    }
    split_arr(cat, bp + BO_CAT, BE_CAT);

    // 2. fc
    gemm3(S_LEN, HDIM, 2 * HDIM, bp + BO_CAT, BE_CAT, bp + BO_FCW, BE_FCW,
          fc_b, nullptr, x);
    // 3. rmsnorm 1 + split
    rmsnorm_kernel<<<S_LEN, 256>>>(x, in_norm_w, h);
    split_arr(h, bp + BO_H, BE_H);
    // 4. qkv
    gemm3(S_LEN, NHEADS * DHEAD, HDIM, bp + BO_H, BE_H, bp + BO_QW, BE_QW,
          nullptr, nullptr, q);
    gemm3(S_LEN, NKVH * DHEAD, HDIM, bp + BO_H, BE_H, bp + BO_KW, BE_KW,
          nullptr, nullptr, k);
    gemm3(S_LEN, NKVH * DHEAD, HDIM, bp + BO_H, BE_H, bp + BO_VW, BE_KW,
          nullptr, nullptr, v);
    // 5. RoPE
    rope_kernel<<<dim3(S_LEN, NHEADS), 64>>>(q, NHEADS * DHEAD);
    rope_kernel<<<dim3(S_LEN, NKVH),  64>>>(k, NKVH * DHEAD);
    // 6. flash attention
    flash_kernel<<<dim3(S_LEN / 64, NHEADS), 256, fa_smem>>>(q, k, v, attn);
    split_arr(attn, bp + BO_ATTN, BE_ATTN);
    // 7. O proj + residual
    gemm3(S_LEN, HDIM, NHEADS * DHEAD, bp + BO_ATTN, BE_ATTN, bp + BO_OW, BE_OW,
          nullptr, x, x2);
    // 8. rmsnorm 2 + split
    rmsnorm_kernel<<<S_LEN, 256>>>(x2, post_norm_w, h2);
    split_arr(h2, bp + BO_H2, BE_H);
    // 9. gate / up
    gemm3(S_LEN, IDIM, HDIM, bp + BO_H2, BE_H, bp + BO_GW, BE_GW,
          nullptr, nullptr, gate);
    gemm3(S_LEN, IDIM, HDIM, bp + BO_H2, BE_H, bp + BO_UW, BE_GW,
          nullptr, nullptr, up);
    // 10. silu*up + split
    {
        const int n4 = S_LEN * IDIM / 4;
        silu_mul_kernel<<<(n4 + 255) / 256, 256>>>(gate, up, gate, n4);
    }
    split_arr(gate, bp + BO_ACT, BE_ACT);
    // 11. down + residual -> out
    gemm3(S_LEN, HDIM, IDIM, bp + BO_ACT, BE_ACT, bp + BO_DW, BE_DW,
          nullptr, x2, (float*)d_out);
}

// round 6
// speedup vs baseline: 2.0061x; 1.0742x over previous
#include <cuda_runtime.h>
#include <cuda_bf16.h>
#include <math.h>
#include <stdint.h>

// Problem constants (B=1)
#define S_LEN   2048
#define HDIM    4096
#define NHEADS  32
#define NKVH    8
#define DHEAD   128
#define IDIM    11008

// ---------------------------------------------------------------------------
// fp32 scratch pool
// ---------------------------------------------------------------------------
#define OFF_X     0                                      // fc out / residual1
#define OFF_Q     (OFF_X    + S_LEN * HDIM)
#define OFF_K     (OFF_Q    + S_LEN * NHEADS * DHEAD)
#define OFF_V     (OFF_K    + S_LEN * NKVH * DHEAD)
#define OFF_X2    (OFF_V    + S_LEN * NKVH * DHEAD)
#define OFF_GATE  (OFF_X2   + S_LEN * HDIM)
#define OFF_UP    (OFF_GATE + S_LEN * IDIM)
#define POOL_SZ   (OFF_UP   + S_LEN * IDIM)

__device__ float g_pool[POOL_SZ];

// ---------------------------------------------------------------------------
// bf16 split pool: for each array, [hi(size) | lo(size)]
// ---------------------------------------------------------------------------
#define BE_CAT   (S_LEN * 2 * HDIM)
#define BE_H     (S_LEN * HDIM)
#define BE_ATTN  (S_LEN * NHEADS * DHEAD)
#define BE_KV    (S_LEN * NKVH * DHEAD)
#define BE_ACT   (S_LEN * IDIM)
#define BE_FCW   (HDIM * 2 * HDIM)
#define BE_QW    (NHEADS * DHEAD * HDIM)
#define BE_KW    (NKVH * DHEAD * HDIM)
#define BE_OW    (HDIM * NHEADS * DHEAD)
#define BE_GW    (IDIM * HDIM)
#define BE_DW    (HDIM * IDIM)

#define BO_CAT   0
#define BO_H     (BO_CAT  + 2 * BE_CAT)
#define BO_ATTN  (BO_H    + 2 * BE_H)
#define BO_H2    (BO_ATTN + 2 * BE_ATTN)
#define BO_ACT   (BO_H2   + 2 * BE_H)
#define BO_FCW   (BO_ACT  + 2 * BE_ACT)
#define BO_QW    (BO_FCW  + 2 * BE_FCW)
#define BO_KW    (BO_QW   + 2 * BE_QW)
#define BO_VW    (BO_KW   + 2 * BE_KW)
#define BO_OW    (BO_VW   + 2 * BE_KW)
#define BO_GW    (BO_OW   + 2 * BE_OW)
#define BO_UW    (BO_GW   + 2 * BE_GW)
#define BO_DW    (BO_UW   + 2 * BE_GW)
#define BO_QB    (BO_DW   + 2 * BE_DW)
#define BO_KB    (BO_QB   + 2 * BE_ATTN)
#define BO_VB    (BO_KB   + 2 * BE_KV)
#define BPOOL_SZ (BO_VB   + 2 * BE_KV)

__device__ __nv_bfloat16 g_bpool[BPOOL_SZ];

// ---------------------------------------------------------------------------
// helpers
// ---------------------------------------------------------------------------
__device__ __forceinline__ uint32_t pack_hi(float a, float b, float* la, float* lb)
{
    __nv_bfloat162 h;
    h.x = __float2bfloat16_rn(a);
    h.y = __float2bfloat16_rn(b);
    *la = a - __bfloat162float(h.x);
    *lb = b - __bfloat162float(h.y);
    uint32_t w; memcpy(&w, &h, 4); return w;
}
__device__ __forceinline__ uint32_t pack_bf(float a, float b)
{
    __nv_bfloat162 h;
    h.x = __float2bfloat16_rn(a);
    h.y = __float2bfloat16_rn(b);
    uint32_t w; memcpy(&w, &h, 4); return w;
}

// ---------------------------------------------------------------------------
// split: hi = bf16(x), lo = bf16(x - hi)   (used for weights + v)
// ---------------------------------------------------------------------------
__global__ void split_kernel(const float* __restrict__ x,
                             __nv_bfloat16* __restrict__ hi,
                             __nv_bfloat16* __restrict__ lo, int n4)
{
    int i = blockIdx.x * blockDim.x + threadIdx.x;
    if (i >= n4) return;
    float4 v = ((const float4*)x)[i];
    float l0, l1, l2, l3;
    uint32_t h0 = pack_hi(v.x, v.y, &l0, &l1);
    uint32_t h1 = pack_hi(v.z, v.w, &l2, &l3);
    ((uint32_t*)hi)[2 * i]     = h0;
    ((uint32_t*)hi)[2 * i + 1] = h1;
    ((uint32_t*)lo)[2 * i]     = pack_bf(l0, l1);
    ((uint32_t*)lo)[2 * i + 1] = pack_bf(l2, l3);
}

// ---------------------------------------------------------------------------
// concat + split fused: cat row = [emb | hid], output bf16 hi/lo only
// ---------------------------------------------------------------------------
__global__ void concat_split_kernel(const float* __restrict__ emb,
                                    const float* __restrict__ hid,
                                    __nv_bfloat16* __restrict__ hi,
                                    __nv_bfloat16* __restrict__ lo)
{
    int i = blockIdx.x * blockDim.x + threadIdx.x;
    const int total4 = S_LEN * 2 * HDIM / 4;
    if (i >= total4) return;
    int row = i / (2 * HDIM / 4);
    int c4  = i % (2 * HDIM / 4);
    float4 v;
    if (c4 < HDIM / 4) v = ((const float4*)emb)[row * (HDIM / 4) + c4];
    else               v = ((const float4*)hid)[row * (HDIM / 4) + (c4 - HDIM / 4)];
    float l0, l1, l2, l3;
    uint32_t h0 = pack_hi(v.x, v.y, &l0, &l1);
    uint32_t h1 = pack_hi(v.z, v.w, &l2, &l3);
    ((uint32_t*)hi)[2 * i]     = h0;
    ((uint32_t*)hi)[2 * i + 1] = h1;
    ((uint32_t*)lo)[2 * i]     = pack_bf(l0, l1);
    ((uint32_t*)lo)[2 * i + 1] = pack_bf(l2, l3);
}

// ---------------------------------------------------------------------------
// Split-bf16 tensor-core NT GEMM (3-stage cp.async pipeline):
//   C[M,N] = Ahi*Bhi^T + Ahi*Blo^T + Alo*Bhi^T (+bias)(+resid)
// CTA 128x128, BK=32, 256 thr (8 warps, 64x32 each). smem rows padded to 20
// words -> conflict-free fragment LDS. Requires M%128==N%128==K%32==0, K>=96.
// ---------------------------------------------------------------------------
#define GSTRIDE  20
#define TILE_W   (128 * GSTRIDE)
#define STAGE_W  (4 * TILE_W)
#define NSTAGE   3
#define GEMM_SMEM_BYTES (NSTAGE * STAGE_W * 4)   // 122880

#define MMA_BF16(ac, a0, a1, a2, a3, b0, b1)                                \
    asm volatile(                                                           \
        "mma.sync.aligned.m16n8k16.row.col.f32.bf16.bf16.f32 "              \
        "{%0,%1,%2,%3}, {%4,%5,%6,%7}, {%8,%9}, {%0,%1,%2,%3};"             \
        : "+f"((ac)[0]), "+f"((ac)[1]), "+f"((ac)[2]), "+f"((ac)[3])        \
        : "r"(a0), "r"(a1), "r"(a2), "r"(a3), "r"(b0), "r"(b1))

#define GEMM_ISSUE(sidx, buf)                                                          \
    do {                                                                               \
        for (int t = 0; t < 4; t++) {                                                  \
            const __nv_bfloat16* src = gsrc[t] + (sidx) * 32 + gc * 16;                \
            uint32_t dst = smem_base + (uint32_t)((buf) * STAGE_W + t * TILE_W + st_w) * 4u; \
            asm volatile("cp.async.cg.shared.global [%0], [%1], 16;\n" :: "r"(dst), "l"(src)); \
            asm volatile("cp.async.cg.shared.global [%0], [%1], 16;\n" :: "r"(dst + 16), "l"(src + 8)); \
        }                                                                              \
        asm volatile("cp.async.commit_group;\n");                                      \
    } while (0)

__global__ __launch_bounds__(256) void gemm_bf16split(
    int M, int N, int K,
    const __nv_bfloat16* __restrict__ Ahi, const __nv_bfloat16* __restrict__ Alo,
    const __nv_bfloat16* __restrict__ Bhi, const __nv_bfloat16* __restrict__ Blo,
    const float* __restrict__ bias, const float* __restrict__ resid,
    float* __restrict__ C)
{
    extern __shared__ uint32_t sw[];

    const int tid  = threadIdx.x;
    const int bx   = blockIdx.x, by = blockIdx.y;
    const int warp = tid >> 5, lane = tid & 31;
    const int wm = warp >> 2, wn = warp & 3;
    const int r  = lane >> 2, c = lane & 3;

    const int gr = tid >> 1;
    const int gc = tid & 1;

    const size_t arow = (size_t)(by * 128 + gr) * K;
    const size_t brow = (size_t)(bx * 128 + gr) * K;
    const __nv_bfloat16* gsrc[4] = { Ahi + arow, Alo + arow, Bhi + brow, Blo + brow };

    const uint32_t smem_base = (uint32_t)__cvta_generic_to_shared(sw);
    const int st_w = gr * GSTRIDE + gc * 8;

    float acc[4][4][4];
    #pragma unroll
    for (int i = 0; i < 4; i++)
        #pragma unroll
        for (int j = 0; j < 4; j++)
            #pragma unroll
            for (int q = 0; q < 4; q++) acc[i][j][q] = 0.f;

    const int nst = K / 32;

    GEMM_ISSUE(0, 0);
    GEMM_ISSUE(1, 1);
    asm volatile("cp.async.wait_group 1;\n");
    __syncthreads();

    for (int s = 0; s < nst; s++) {
        const int cur = s % 3;
        if (s + 2 < nst) GEMM_ISSUE(s + 2, (s + 2) % 3);

        const uint32_t* Ah = sw + cur * STAGE_W;
        const uint32_t* Al = Ah + TILE_W;
        const uint32_t* Bh = Ah + 2 * TILE_W;
        const uint32_t* Bl = Ah + 3 * TILE_W;

        #pragma unroll
        for (int k0 = 0; k0 < 2; k0++) {
            const int kw = k0 * 8;
            uint32_t ah[4][4], al[4][4];
            #pragma unroll
            for (int i = 0; i < 4; i++) {
                const int m  = wm * 64 + i * 16 + r;
                const int o1 = m * GSTRIDE + kw + c;
                const int o2 = (m + 8) * GSTRIDE + kw + c;
                ah[i][0] = Ah[o1];     ah[i][1] = Ah[o2];
                ah[i][2] = Ah[o1 + 4]; ah[i][3] = Ah[o2 + 4];
                al[i][0] = Al[o1];     al[i][1] = Al[o2];
                al[i][2] = Al[o1 + 4]; al[i][3] = Al[o2 + 4];
            }
            #pragma unroll
            for (int j = 0; j < 4; j++) {
                const int n  = wn * 32 + j * 8 + r;
                const int ob = n * GSTRIDE + kw + c;
                const uint32_t bh0 = Bh[ob], bh1 = Bh[ob + 4];
                const uint32_t bl0 = Bl[ob], bl1 = Bl[ob + 4];
                #pragma unroll
                for (int i = 0; i < 4; i++) {
                    MMA_BF16(acc[i][j], ah[i][0], ah[i][1], ah[i][2], ah[i][3], bh0, bh1);
                    MMA_BF16(acc[i][j], ah[i][0], ah[i][1], ah[i][2], ah[i][3], bl0, bl1);
                    MMA_BF16(acc[i][j], al[i][0], al[i][1], al[i][2], al[i][3], bh0, bh1);
                }
            }
        }

        if (s + 1 < nst) {
            if (s + 2 < nst) asm volatile("cp.async.wait_group 1;\n");
            else             asm volatile("cp.async.wait_group 0;\n");
            __syncthreads();
        }
    }

    #pragma unroll
    for (int j = 0; j < 4; j++) {
        const int col = bx * 128 + wn * 32 + j * 8 + 2 * c;
        float2 bv = make_float2(0.f, 0.f);
        if (bias) bv = *(const float2*)(bias + col);
        #pragma unroll
        for (int i = 0; i < 4; i++) {
            const int m1 = by * 128 + wm * 64 + i * 16 + r;
            const int m2 = m1 + 8;
            float2 o0 = make_float2(acc[i][j][0] + bv.x, acc[i][j][1] + bv.y);
            float2 o1 = make_float2(acc[i][j][2] + bv.x, acc[i][j][3] + bv.y);
            size_t p0 = (size_t)m1 * N + col;
            size_t p1 = (size_t)m2 * N + col;
            if (resid) {
                float2 r0 = *(const float2*)(resid + p0);
                float2 r1 = *(const float2*)(resid + p1);
                o0.x += r0.x; o0.y += r0.y;
                o1.x += r1.x; o1.y += r1.y;
            }
            *(float2*)(C + p0) = o0;
            *(float2*)(C + p1) = o1;
        }
    }
}

// ---------------------------------------------------------------------------
// RMSNorm + split fused: bf16 hi/lo output
// ---------------------------------------------------------------------------
__global__ __launch_bounds__(256) void rmsnorm_split_kernel(
    const float* __restrict__ x, const float* __restrict__ w,
    __nv_bfloat16* __restrict__ hi, __nv_bfloat16* __restrict__ lo)
{
    const int row = blockIdx.x;
    const float4* xr = (const float4*)(x + (size_t)row * HDIM);
    float ss = 0.f;
    for (int i = threadIdx.x; i < HDIM / 4; i += 256) {
        float4 v = xr[i];
        ss += v.x * v.x + v.y * v.y + v.z * v.z + v.w * v.w;
    }
    #pragma unroll
    for (int o = 16; o > 0; o >>= 1) ss += __shfl_xor_sync(0xffffffffu, ss, o);
    __shared__ float red[8];
    __shared__ float s_scale;
    if ((threadIdx.x & 31) == 0) red[threadIdx.x >> 5] = ss;
    __syncthreads();
    if (threadIdx.x == 0) {
        float tot = 0.f;
        #pragma unroll
        for (int i = 0; i < 8; i++) tot += red[i];
        s_scale = rsqrtf(tot / (float)HDIM + 1e-6f);
    }
    __syncthreads();
    const float sc = s_scale;
    const float4* wr = (const float4*)w;
    uint32_t* hw = (uint32_t*)(hi + (size_t)row * HDIM);
    uint32_t* lw = (uint32_t*)(lo + (size_t)row * HDIM);
    for (int i = threadIdx.x; i < HDIM / 4; i += 256) {
        float4 v = xr[i], ww = wr[i];
        float y0 = v.x * sc * ww.x, y1 = v.y * sc * ww.y;
        float y2 = v.z * sc * ww.z, y3 = v.w * sc * ww.w;
        float l0, l1, l2, l3;
        hw[2 * i]     = pack_hi(y0, y1, &l0, &l1);
        hw[2 * i + 1] = pack_hi(y2, y3, &l2, &l3);
        lw[2 * i]     = pack_bf(l0, l1);
        lw[2 * i + 1] = pack_bf(l2, l3);
    }
}

// ---------------------------------------------------------------------------
// RoPE + split fused. grid (S, heads), 64 threads. position == row index.
// ---------------------------------------------------------------------------
__global__ void rope_split_kernel(const float* __restrict__ src,
                                  __nv_bfloat16* __restrict__ hi,
                                  __nv_bfloat16* __restrict__ lo)
{
    const int s = blockIdx.x;
    const int hh = blockIdx.y;
    const int d = threadIdx.x;  // 0..63
    const size_t o = (size_t)s * gridDim.y * DHEAD + hh * DHEAD;
    const double p = (double)s;
    const double invf = exp(-(double)d * 0.14391156831212787);
    const double ph = p * invf;
    const float cc = (float)cos(ph);
    const float si = (float)sin(ph);
    const float x1 = src[o + d];
    const float x2 = src[o + d + 64];
    const float y1 = x1 * cc - x2 * si;
    const float y2 = x2 * cc + x1 * si;
    __nv_bfloat16 h1 = __float2bfloat16_rn(y1);
    __nv_bfloat16 h2 = __float2bfloat16_rn(y2);
    hi[o + d]      = h1;
    hi[o + d + 64] = h2;
    lo[o + d]      = __float2bfloat16_rn(y1 - __bfloat162float(h1));
    lo[o + d + 64] = __float2bfloat16_rn(y2 - __bfloat162float(h2));
}

// ---------------------------------------------------------------------------
// Tensor-core flash attention (split-bf16, 3-term), causal.
// grid = (S/64, NH), 256 threads. BM=BN=64, D=128, GQA rep 4.
// Output written directly as bf16 hi/lo (input to O-proj GEMM).
// ---------------------------------------------------------------------------
#define QSTR 68     // words per 128-half row (Q/K/V tiles)
#define PSTR 36     // words per 64-half row (P tiles)
#define FL_QH 0
#define FL_QL (FL_QH + 64 * QSTR)
#define FL_KH (FL_QL + 64 * QSTR)
#define FL_KL (FL_KH + 64 * QSTR)
#define FL_VH (FL_KL + 64 * QSTR)
#define FL_VL (FL_VH + 64 * QSTR)
#define FL_PH (FL_VL + 64 * QSTR)
#define FL_PL (FL_PH + 64 * PSTR)
#define FL_SB (FL_PL + 64 * PSTR)     // fp32 scores [64][66]
#define FL_RM (FL_SB + 64 * 66)
#define FL_RL (FL_RM + 64)
#define FL_RA (FL_RL + 64)
#define FL_WORDS (FL_RA + 64)
#define FL_SMEM_BYTES (FL_WORDS * 4)  // 140544

__global__ __launch_bounds__(256) void flash_tc(
    const uint32_t* __restrict__ qh, const uint32_t* __restrict__ ql,
    const uint32_t* __restrict__ kh, const uint32_t* __restrict__ kl,
    const uint32_t* __restrict__ vh, const uint32_t* __restrict__ vl,
    __nv_bfloat16* __restrict__ ahi, __nv_bfloat16* __restrict__ alo)
{
    extern __shared__ uint32_t sw[];
    float* smf = (float*)sw;

    const int tid = threadIdx.x, warp = tid >> 5, lane = tid & 31;
    const int wm = warp >> 2, wn = warp & 3;     // 2(M) x 4(N)
    const int r = lane >> 2, c = lane & 3;
    const int h = blockIdx.y, m0 = blockIdx.x * 64, kvh = h >> 2;
    const uint32_t smem_b = (uint32_t)__cvta_generic_to_shared(sw);
    const float scale = 0.08838834764831845f;

    // load Q tile (hi/lo), 64 rows x 64 words
    for (int i = tid; i < 64 * 64; i += 256) {
        const int row = i >> 6, w = i & 63;
        const size_t g = (size_t)(m0 + row) * 2048 + h * 64 + w;
        sw[FL_QH + row * QSTR + w] = qh[g];
        sw[FL_QL + row * QSTR + w] = ql[g];
    }
    if (tid < 64) { smf[FL_RM + tid] = -INFINITY; smf[FL_RL + tid] = 0.f; }

    float accO[2][4][4];
    #pragma unroll
    for (int i = 0; i < 2; i++)
        #pragma unroll
        for (int j = 0; j < 4; j++)
            #pragma unroll
            for (int q = 0; q < 4; q++) accO[i][j][q] = 0.f;

    const int ntiles = blockIdx.x + 1;
    for (int t = 0; t < ntiles; ++t) {
        const int n0 = t * 64;
        __syncthreads();
        // load K and V tiles (hi/lo)
        for (int i = tid; i < 64 * 64; i += 256) {
            const int row = i >> 6, w = i & 63;
            const size_t g = (size_t)(n0 + row) * 512 + kvh * 64 + w;
            sw[FL_KH + row * QSTR + w] = kh[g];
            sw[FL_KL + row * QSTR + w] = kl[g];
            sw[FL_VH + row * QSTR + w] = vh[g];
            sw[FL_VL + row * QSTR + w] = vl[g];
        }
        __syncthreads();

        // ---- S = Q K^T (3-term) : warp tile 32x16 ----
        float accS[2][2][4];
        #pragma unroll
        for (int i = 0; i < 2; i++)
            #pragma unroll
            for (int j = 0; j < 2; j++)
                #pragma unroll
                for (int q = 0; q < 4; q++) accS[i][j][q] = 0.f;

        #pragma unroll
        for (int ks = 0; ks < 8; ks++) {
            const int kw = ks * 8;
            uint32_t qa[2][4], qb[2][4];
            #pragma unroll
            for (int i = 0; i < 2; i++) {
                const int m = wm * 32 + i * 16 + r;
                const int o1 = m * QSTR + kw + c;
                const int o2 = (m + 8) * QSTR + kw + c;
                qa[i][0] = sw[FL_QH + o1];     qa[i][1] = sw[FL_QH + o2];
                qa[i][2] = sw[FL_QH + o1 + 4]; qa[i][3] = sw[FL_QH + o2 + 4];
                qb[i][0] = sw[FL_QL + o1];     qb[i][1] = sw[FL_QL + o2];
                qb[i][2] = sw[FL_QL + o1 + 4]; qb[i][3] = sw[FL_QL + o2 + 4];
            }
            #pragma unroll
            for (int j = 0; j < 2; j++) {
                const int n = wn * 16 + j * 8 + r;
                const int ob = n * QSTR + kw + c;
                const uint32_t kh0 = sw[FL_KH + ob], kh1 = sw[FL_KH + ob + 4];
                const uint32_t kl0 = sw[FL_KL + ob], kl1 = sw[FL_KL + ob + 4];
                #pragma unroll
                for (int i = 0; i < 2; i++) {
                    MMA_BF16(accS[i][j], qa[i][0], qa[i][1], qa[i][2], qa[i][3], kh0, kh1);
                    MMA_BF16(accS[i][j], qa[i][0], qa[i][1], qa[i][2], qa[i][3], kl0, kl1);
                    MMA_BF16(accS[i][j], qb[i][0], qb[i][1], qb[i][2], qb[i][3], kh0, kh1);
                }
            }
        }

        // write scores (scaled, causal-masked) to fp32 smem
        #pragma unroll
        for (int i = 0; i < 2; i++) {
            const int row0 = wm * 32 + i * 16 + r;
            #pragma unroll
            for (int j = 0; j < 2; j++) {
                const int col0 = wn * 16 + j * 8 + 2 * c;
                float v0 = accS[i][j][0] * scale;
                float v1 = accS[i][j][1] * scale;
                float v2 = accS[i][j][2] * scale;
                float v3 = accS[i][j][3] * scale;
                if (n0 + col0     > m0 + row0)     v0 = -1e30f;
                if (n0 + col0 + 1 > m0 + row0)     v1 = -1e30f;
                if (n0 + col0     > m0 + row0 + 8) v2 = -1e30f;
                if (n0 + col0 + 1 > m0 + row0 + 8) v3 = -1e30f;
                smf[FL_SB + row0 * 66 + col0]           = v0;
                smf[FL_SB + row0 * 66 + col0 + 1]       = v1;
                smf[FL_SB + (row0 + 8) * 66 + col0]     = v2;
                smf[FL_SB + (row0 + 8) * 66 + col0 + 1] = v3;
            }
        }
        __syncthreads();

        // online softmax (one thread per q row) -> P hi/lo bf16
        if (tid < 64) {
            float* pr = smf + FL_SB + tid * 66;
            float mloc = -INFINITY;
            #pragma unroll 8
            for (int cc = 0; cc < 64; ++cc) mloc = fmaxf(mloc, pr[cc]);
            const float mold = smf[FL_RM + tid];
            const float mnew = fmaxf(mold, mloc);
            const float alpha = (mold == -INFINITY) ? 0.f : expf(mold - mnew);
            float lsum = 0.f;
            #pragma unroll 8
            for (int cw = 0; cw < 32; ++cw) {
                const float p0 = expf(pr[2 * cw]     - mnew);
                const float p1 = expf(pr[2 * cw + 1] - mnew);
                lsum += p0 + p1;
                float l0, l1;
                sw[FL_PH + tid * PSTR + cw] = pack_hi(p0, p1, &l0, &l1);
                sw[FL_PL + tid * PSTR + cw] = pack_bf(l0, l1);
            }
            smf[FL_RL + tid] = smf[FL_RL + tid] * alpha + lsum;
            smf[FL_RM + tid] = mnew;
            smf[FL_RA + tid] = alpha;
        }
        __syncthreads();

        // rescale O accumulators
        float al0[2], al1[2];
        #pragma unroll
        for (int i = 0; i < 2; i++) {
            al0[i] = smf[FL_RA + wm * 32 + i * 16 + r];
            al1[i] = smf[FL_RA + wm * 32 + i * 16 + r + 8];
        }
        #pragma unroll
        for (int i = 0; i < 2; i++)
            #pragma unroll
            for (int j = 0; j < 4; j++) {
                accO[i][j][0] *= al0[i]; accO[i][j][1] *= al0[i];
                accO[i][j][2] *= al1[i]; accO[i][j][3] *= al1[i];
            }

        // ---- O += P V (3-term) : warp tile 32x32 over D ----
        #pragma unroll
        for (int ks = 0; ks < 4; ks++) {
            const int kw = ks * 8;
            uint32_t pa[2][4], pb[2][4];
            #pragma unroll
            for (int i = 0; i < 2; i++) {
                const int m = wm * 32 + i * 16 + r;
                const int o1 = m * PSTR + kw + c;
                const int o2 = (m + 8) * PSTR + kw + c;
                pa[i][0] = sw[FL_PH + o1];     pa[i][1] = sw[FL_PH + o2];
                pa[i][2] = sw[FL_PH + o1 + 4]; pa[i][3] = sw[FL_PH + o2 + 4];
                pb[i][0] = sw[FL_PL + o1];     pb[i][1] = sw[FL_PL + o2];
                pb[i][2] = sw[FL_PL + o1 + 4]; pb[i][3] = sw[FL_PL + o2 + 4];
            }
            #pragma unroll
            for (int j = 0; j < 4; j++) {
                const int jcol = wn * 32 + j * 8;
                const uint32_t addr_h = smem_b +
                    (uint32_t)(FL_VH + (ks * 16 + (lane & 15)) * QSTR + (jcol >> 1)) * 4u;
                const uint32_t addr_l = smem_b +
                    (uint32_t)(FL_VL + (ks * 16 + (lane & 15)) * QSTR + (jcol >> 1)) * 4u;
                uint32_t vh0, vh1, vl0, vl1;
                asm volatile("ldmatrix.sync.aligned.m8n8.x2.trans.shared.b16 {%0,%1},[%2];"
                             : "=r"(vh0), "=r"(vh1) : "r"(addr_h));
                asm volatile("ldmatrix.sync.aligned.m8n8.x2.trans.shared.b16 {%0,%1},[%2];"
                             : "=r"(vl0), "=r"(vl1) : "r"(addr_l));
                #pragma unroll
                for (int i = 0; i < 2; i++) {
                    MMA_BF16(accO[i][j], pa[i][0], pa[i][1], pa[i][2], pa[i][3], vh0, vh1);
                    MMA_BF16(accO[i][j], pa[i][0], pa[i][1], pa[i][2], pa[i][3], vl0, vl1);
                    MMA_BF16(accO[i][j], pb[i][0], pb[i][1], pb[i][2], pb[i][3], vh0, vh1);
                }
            }
        }
    }

    __syncthreads();
    // epilogue: normalize, split to bf16 hi/lo, store
    #pragma unroll
    for (int i = 0; i < 2; i++) {
        const int row0 = wm * 32 + i * 16 + r;
        const float inv0 = 1.f / smf[FL_RL + row0];
        const float inv1 = 1.f / smf[FL_RL + row0 + 8];
        #pragma unroll
        for (int j = 0; j < 4; j++) {
            const int col = wn * 32 + j * 8 + 2 * c;
            const float x0 = accO[i][j][0] * inv0, x1 = accO[i][j][1] * inv0;
            const float x2 = accO[i][j][2] * inv1, x3 = accO[i][j][3] * inv1;
            const size_t g0 = (size_t)(m0 + row0) * 4096 + h * 128 + col;
            const size_t g1 = (size_t)(m0 + row0 + 8) * 4096 + h * 128 + col;
            float l0, l1, l2, l3;
            *(uint32_t*)(ahi + g0) = pack_hi(x0, x1, &l0, &l1);
            *(uint32_t*)(ahi + g1) = pack_hi(x2, x3, &l2, &l3);
            *(uint32_t*)(alo + g0) = pack_bf(l0, l1);
            *(uint32_t*)(alo + g1) = pack_bf(l2, l3);
        }
    }
}

// ---------------------------------------------------------------------------
// silu(gate)*up + split fused
// ---------------------------------------------------------------------------
__global__ void silu_mul_split_kernel(const float* __restrict__ g,
                                      const float* __restrict__ u,
                                      __nv_bfloat16* __restrict__ hi,
                                      __nv_bfloat16* __restrict__ lo, int n4)
{
    int i = blockIdx.x * blockDim.x + threadIdx.x;
    if (i >= n4) return;
    float4 gg = ((const float4*)g)[i];
    float4 uu = ((const float4*)u)[i];
    float y0 = gg.x / (1.f + expf(-gg.x)) * uu.x;
    float y1 = gg.y / (1.f + expf(-gg.y)) * uu.y;
    float y2 = gg.z / (1.f + expf(-gg.z)) * uu.z;
    float y3 = gg.w / (1.f + expf(-gg.w)) * uu.w;
    float l0, l1, l2, l3;
    ((uint32_t*)hi)[2 * i]     = pack_hi(y0, y1, &l0, &l1);
    ((uint32_t*)hi)[2 * i + 1] = pack_hi(y2, y3, &l2, &l3);
    ((uint32_t*)lo)[2 * i]     = pack_bf(l0, l1);
    ((uint32_t*)lo)[2 * i + 1] = pack_bf(l2, l3);
}

// ---------------------------------------------------------------------------
// Host orchestration
// ---------------------------------------------------------------------------
static inline void split_arr(const float* x, __nv_bfloat16* base, int n)
{
    split_kernel<<<(n / 4 + 255) / 256, 256>>>(x, base, base + n, n / 4);
}

static inline void gemm3(int M, int N, int K,
                         const __nv_bfloat16* Ab, int Aelems,
                         const __nv_bfloat16* Bb, int Belems,
                         const float* bias, const float* resid, float* C)
{
    gemm_bf16split<<<dim3(N / 128, M / 128), 256, GEMM_SMEM_BYTES>>>(
        M, N, K, Ab, Ab + Aelems, Bb, Bb + Belems, bias, resid, C);
}

extern "C" void kernel_launch(void* const* d_in, const int* in_sizes, int n_in,
                              void* d_out, int out_size)
{
    const float* hidden      = (const float*)d_in[0];
    const float* embeds      = (const float*)d_in[1];
    // d_in[2] attention_mask: all ones -> pad mask zero
    const float* fc_w        = (const float*)d_in[3];
    const float* fc_b        = (const float*)d_in[4];
    const float* in_norm_w   = (const float*)d_in[5];
    const float* q_w         = (const float*)d_in[6];
    const float* k_w         = (const float*)d_in[7];
    const float* v_w         = (const float*)d_in[8];
    const float* o_w         = (const float*)d_in[9];
    const float* post_norm_w = (const float*)d_in[10];
    const float* gate_w      = (const float*)d_in[11];
    const float* up_w        = (const float*)d_in[12];
    const float* down_w      = (const float*)d_in[13];
    // d_in[14] position_ids == arange(S)

    float* pool = nullptr;
    cudaGetSymbolAddress((void**)&pool, g_pool);
    float* x    = pool + OFF_X;
    float* q    = pool + OFF_Q;
    float* k    = pool + OFF_K;
    float* v    = pool + OFF_V;
    float* x2   = pool + OFF_X2;
    float* gate = pool + OFF_GATE;
    float* up   = pool + OFF_UP;

    __nv_bfloat16* bp = nullptr;
    cudaGetSymbolAddress((void**)&bp, g_bpool);

    cudaFuncSetAttribute(flash_tc,
                         cudaFuncAttributeMaxDynamicSharedMemorySize, FL_SMEM_BYTES);
    cudaFuncSetAttribute(gemm_bf16split,
                         cudaFuncAttributeMaxDynamicSharedMemorySize, GEMM_SMEM_BYTES);

    // weight splits
    split_arr(fc_w,   bp + BO_FCW, BE_FCW);
    split_arr(q_w,    bp + BO_QW,  BE_QW);
    split_arr(k_w,    bp + BO_KW,  BE_KW);
    split_arr(v_w,    bp + BO_VW,  BE_KW);
    split_arr(o_w,    bp + BO_OW,  BE_OW);
    split_arr(gate_w, bp + BO_GW,  BE_GW);
    split_arr(up_w,   bp + BO_UW,  BE_GW);
    split_arr(down_w, bp + BO_DW,  BE_DW);

    // 1. concat+split
    {
        const int n4 = S_LEN * 2 * HDIM / 4;
        concat_split_kernel<<<(n4 + 255) / 256, 256>>>(
            embeds, hidden, bp + BO_CAT, bp + BO_CAT + BE_CAT);
    }
    // 2. fc
    gemm3(S_LEN, HDIM, 2 * HDIM, bp + BO_CAT, BE_CAT, bp + BO_FCW, BE_FCW,
          fc_b, nullptr, x);
    // 3. rmsnorm1 + split
    rmsnorm_split_kernel<<<S_LEN, 256>>>(x, in_norm_w,
                                         bp + BO_H, bp + BO_H + BE_H);
    // 4. qkv
    gemm3(S_LEN, NHEADS * DHEAD, HDIM, bp + BO_H, BE_H, bp + BO_QW, BE_QW,
          nullptr, nullptr, q);
    gemm3(S_LEN, NKVH * DHEAD, HDIM, bp + BO_H, BE_H, bp + BO_KW, BE_KW,
          nullptr, nullptr, k);
    gemm3(S_LEN, NKVH * DHEAD, HDIM, bp + BO_H, BE_H, bp + BO_VW, BE_KW,
          nullptr, nullptr, v);
    // 5. RoPE + split (q,k); plain split (v)
    rope_split_kernel<<<dim3(S_LEN, NHEADS), 64>>>(q, bp + BO_QB, bp + BO_QB + BE_ATTN);
    rope_split_kernel<<<dim3(S_LEN, NKVH),  64>>>(k, bp + BO_KB, bp + BO_KB + BE_KV);
    split_arr(v, bp + BO_VB, BE_KV);
    // 6. flash attention (tensor-core)
    flash_tc<<<dim3(S_LEN / 64, NHEADS), 256, FL_SMEM_BYTES>>>(
        (const uint32_t*)(bp + BO_QB), (const uint32_t*)(bp + BO_QB + BE_ATTN),
        (const uint32_t*)(bp + BO_KB), (const uint32_t*)(bp + BO_KB + BE_KV),
        (const uint32_t*)(bp + BO_VB), (const uint32_t*)(bp + BO_VB + BE_KV),
        bp + BO_ATTN, bp + BO_ATTN + BE_ATTN);
    // 7. O proj + residual
    gemm3(S_LEN, HDIM, NHEADS * DHEAD, bp + BO_ATTN, BE_ATTN, bp + BO_OW, BE_OW,
          nullptr, x, x2);
    // 8. rmsnorm2 + split
    rmsnorm_split_kernel<<<S_LEN, 256>>>(x2, post_norm_w,
                                         bp + BO_H2, bp + BO_H2 + BE_H);
    // 9. gate / up
    gemm3(S_LEN, IDIM, HDIM, bp + BO_H2, BE_H, bp + BO_GW, BE_GW,
          nullptr, nullptr, gate);
    gemm3(S_LEN, IDIM, HDIM, bp + BO_H2, BE_H, bp + BO_UW, BE_GW,
          nullptr, nullptr, up);
    // 10. silu*up + split
    {
        const int n4 = S_LEN * IDIM / 4;
        silu_mul_split_kernel<<<(n4 + 255) / 256, 256>>>(
            gate, up, bp + BO_ACT, bp + BO_ACT + BE_ACT, n4);
    }
    // 11. down + residual -> out
    gemm3(S_LEN, HDIM, IDIM, bp + BO_ACT, BE_ACT, bp + BO_DW, BE_DW,
          nullptr, x2, (float*)d_out);
}

// round 8
// speedup vs baseline: 2.4160x; 1.2043x over previous
#include <cuda_runtime.h>
#include <cuda_bf16.h>
#include <math.h>
#include <stdint.h>

// Problem constants (B=1)
#define S_LEN   2048
#define HDIM    4096
#define NHEADS  32
#define NKVH    8
#define DHEAD   128
#define IDIM    11008

// ---------------------------------------------------------------------------
// fp32 scratch pool
// ---------------------------------------------------------------------------
#define OFF_X     0
#define OFF_Q     (OFF_X    + S_LEN * HDIM)
#define OFF_K     (OFF_Q    + S_LEN * NHEADS * DHEAD)
#define OFF_V     (OFF_K    + S_LEN * NKVH * DHEAD)
#define OFF_X2    (OFF_V    + S_LEN * NKVH * DHEAD)
#define OFF_GATE  (OFF_X2   + S_LEN * HDIM)
#define OFF_UP    (OFF_GATE + S_LEN * IDIM)
#define POOL_SZ   (OFF_UP   + S_LEN * IDIM)

__device__ float g_pool[POOL_SZ];

// ---------------------------------------------------------------------------
// bf16 split pool: for each array, [hi(size) | lo(size)]
// ---------------------------------------------------------------------------
#define BE_CAT   (S_LEN * 2 * HDIM)
#define BE_H     (S_LEN * HDIM)
#define BE_ATTN  (S_LEN * NHEADS * DHEAD)
#define BE_KV    (S_LEN * NKVH * DHEAD)
#define BE_ACT   (S_LEN * IDIM)
#define BE_FCW   (HDIM * 2 * HDIM)
#define BE_QW    (NHEADS * DHEAD * HDIM)
#define BE_KW    (NKVH * DHEAD * HDIM)
#define BE_OW    (HDIM * NHEADS * DHEAD)
#define BE_GW    (IDIM * HDIM)
#define BE_DW    (HDIM * IDIM)

#define BO_CAT   0
#define BO_H     (BO_CAT  + 2 * BE_CAT)
#define BO_ATTN  (BO_H    + 2 * BE_H)
#define BO_H2    (BO_ATTN + 2 * BE_ATTN)
#define BO_ACT   (BO_H2   + 2 * BE_H)
#define BO_FCW   (BO_ACT  + 2 * BE_ACT)
#define BO_QW    (BO_FCW  + 2 * BE_FCW)
#define BO_KW    (BO_QW   + 2 * BE_QW)
#define BO_VW    (BO_KW   + 2 * BE_KW)
#define BO_OW    (BO_VW   + 2 * BE_KW)
#define BO_GW    (BO_OW   + 2 * BE_OW)
#define BO_UW    (BO_GW   + 2 * BE_GW)
#define BO_DW    (BO_UW   + 2 * BE_GW)
#define BO_QB    (BO_DW   + 2 * BE_DW)
#define BO_KB    (BO_QB   + 2 * BE_ATTN)
#define BO_VB    (BO_KB   + 2 * BE_KV)
#define BPOOL_SZ (BO_VB   + 2 * BE_KV)

__device__ __nv_bfloat16 g_bpool[BPOOL_SZ];

// ---------------------------------------------------------------------------
// helpers
// ---------------------------------------------------------------------------
__device__ __forceinline__ uint32_t pack_hi(float a, float b, float* la, float* lb)
{
    __nv_bfloat162 h;
    h.x = __float2bfloat16_rn(a);
    h.y = __float2bfloat16_rn(b);
    *la = a - __bfloat162float(h.x);
    *lb = b - __bfloat162float(h.y);
    uint32_t w; memcpy(&w, &h, 4); return w;
}
__device__ __forceinline__ uint32_t pack_bf(float a, float b)
{
    __nv_bfloat162 h;
    h.x = __float2bfloat16_rn(a);
    h.y = __float2bfloat16_rn(b);
    uint32_t w; memcpy(&w, &h, 4); return w;
}
__device__ __forceinline__ uint32_t smem_u32(const void* p)
{
    uint32_t a;
    asm("{ .reg .u64 t; cvta.to.shared.u64 t, %1; cvt.u32.u64 %0, t; }"
        : "=r"(a) : "l"(p));
    return a;
}

#define MMA_BF16(ac, a0, a1, a2, a3, b0, b1)                                \
    asm volatile(                                                           \
        "mma.sync.aligned.m16n8k16.row.col.f32.bf16.bf16.f32 "              \
        "{%0,%1,%2,%3}, {%4,%5,%6,%7}, {%8,%9}, {%0,%1,%2,%3};"             \
        : "+f"((ac)[0]), "+f"((ac)[1]), "+f"((ac)[2]), "+f"((ac)[3])        \
        : "r"(a0), "r"(a1), "r"(a2), "r"(a3), "r"(b0), "r"(b1))

#define LDSM_X4(rr, addr)                                                   \
    asm volatile("ldmatrix.sync.aligned.m8n8.x4.shared.b16 {%0,%1,%2,%3}, [%4];" \
        : "=r"((rr)[0]), "=r"((rr)[1]), "=r"((rr)[2]), "=r"((rr)[3]) : "r"(addr))

// ---------------------------------------------------------------------------
// split / concat_split
// ---------------------------------------------------------------------------
__global__ void split_kernel(const float* __restrict__ x,
                             __nv_bfloat16* __restrict__ hi,
                             __nv_bfloat16* __restrict__ lo, int n4)
{
    int i = blockIdx.x * blockDim.x + threadIdx.x;
    if (i >= n4) return;
    float4 v = ((const float4*)x)[i];
    float l0, l1, l2, l3;
    uint32_t h0 = pack_hi(v.x, v.y, &l0, &l1);
    uint32_t h1 = pack_hi(v.z, v.w, &l2, &l3);
    ((uint32_t*)hi)[2 * i]     = h0;
    ((uint32_t*)hi)[2 * i + 1] = h1;
    ((uint32_t*)lo)[2 * i]     = pack_bf(l0, l1);
    ((uint32_t*)lo)[2 * i + 1] = pack_bf(l2, l3);
}

__global__ void concat_split_kernel(const float* __restrict__ emb,
                                    const float* __restrict__ hid,
                                    __nv_bfloat16* __restrict__ hi,
                                    __nv_bfloat16* __restrict__ lo)
{
    int i = blockIdx.x * blockDim.x + threadIdx.x;
    const int total4 = S_LEN * 2 * HDIM / 4;
    if (i >= total4) return;
    int row = i / (2 * HDIM / 4);
    int c4  = i % (2 * HDIM / 4);
    float4 v;
    if (c4 < HDIM / 4) v = ((const float4*)emb)[row * (HDIM / 4) + c4];
    else               v = ((const float4*)hid)[row * (HDIM / 4) + (c4 - HDIM / 4)];
    float l0, l1, l2, l3;
    uint32_t h0 = pack_hi(v.x, v.y, &l0, &l1);
    uint32_t h1 = pack_hi(v.z, v.w, &l2, &l3);
    ((uint32_t*)hi)[2 * i]     = h0;
    ((uint32_t*)hi)[2 * i + 1] = h1;
    ((uint32_t*)lo)[2 * i]     = pack_bf(l0, l1);
    ((uint32_t*)lo)[2 * i + 1] = pack_bf(l2, l3);
}

// ===========================================================================
// Split-bf16 mma.sync NT GEMM, CTA 128x256, warp tile 64x64, ldmatrix frags.
//   C[M,N] = Ahi*Bhi^T + Ahi*Blo^T + Alo*Bhi^T (+bias)(+resid)
// 256 threads = 8 warps (2 M x 4 N). K-chunk 32, 3-stage cp.async.
// smem rows padded to 20 words (80B): conflict-free ldmatrix + stores.
// Requires M%128==0, N%256==0, K%32==0, K>=96.
// ===========================================================================
#define GSTRIDE  20
#define W_AH 0
#define W_AL (128 * GSTRIDE)          // 2560
#define W_BH (2 * 128 * GSTRIDE)      // 5120
#define W_BL (W_BH + 256 * GSTRIDE)   // 10240
#define STAGE_W  (W_BL + 256 * GSTRIDE)  // 15360 words
#define NSTAGE   3
#define GEMM_SMEM_BYTES (NSTAGE * STAGE_W * 4)   // 184320

#define GEMM_ISSUE(sidx, buf)                                                          \
    do {                                                                               \
        const uint32_t bufb = smem_base + (uint32_t)(buf) * (STAGE_W * 4);             \
        _Pragma("unroll")                                                              \
        for (int t = 0; t < 12; t++) {                                                 \
            const int idx = tid + t * 256;                                             \
            const int row = idx >> 2, ch = idx & 3;                                    \
            const __nv_bfloat16* src;                                                  \
            uint32_t dw;                                                               \
            if (row < 256) {                                                           \
                src = (row < 128 ? gah : gal) + (size_t)(row & 127) * K                \
                      + (sidx) * 32 + ch * 8;                                          \
                dw = (row < 128 ? W_AH : W_AL) + (row & 127) * GSTRIDE + ch * 4;       \
            } else {                                                                   \
                const int r2 = row - 256;                                              \
                src = (r2 < 256 ? gbh : gbl) + (size_t)(r2 & 255) * K                  \
                      + (sidx) * 32 + ch * 8;                                          \
                dw = (r2 < 256 ? W_BH : W_BL) + (r2 & 255) * GSTRIDE + ch * 4;         \
            }                                                                          \
            asm volatile("cp.async.cg.shared.global [%0], [%1], 16;\n"                 \
                         :: "r"(bufb + dw * 4u), "l"(src));                            \
        }                                                                              \
        asm volatile("cp.async.commit_group;\n");                                      \
    } while (0)

__global__ __launch_bounds__(256) void gemm_bf16split(
    int M, int N, int K,
    const __nv_bfloat16* __restrict__ Ahi, const __nv_bfloat16* __restrict__ Alo,
    const __nv_bfloat16* __restrict__ Bhi, const __nv_bfloat16* __restrict__ Blo,
    const float* __restrict__ bias, const float* __restrict__ resid,
    float* __restrict__ C)
{
    extern __shared__ uint32_t sw[];

    const int tid  = threadIdx.x;
    const int bx   = blockIdx.x, by = blockIdx.y;
    const int warp = tid >> 5, lane = tid & 31;
    const int wm = warp >> 2, wn = warp & 3;     // 2(M) x 4(N)
    const int r  = lane >> 2, c = lane & 3;

    const __nv_bfloat16* gah = Ahi + (size_t)(by * 128) * K;
    const __nv_bfloat16* gal = Alo + (size_t)(by * 128) * K;
    const __nv_bfloat16* gbh = Bhi + (size_t)(bx * 256) * K;
    const __nv_bfloat16* gbl = Blo + (size_t)(bx * 256) * K;

    const uint32_t smem_base = (uint32_t)__cvta_generic_to_shared(sw);

    // ldmatrix per-lane address components (word offsets within a stage)
    // A tiles: row = wm*64 + i*16 + (lane&15); koff16 word = (lane>>4)*4
    const int a_row = wm * 64 + (lane & 15);
    const int a_kw  = (lane >> 4) * 4;
    // B pair tiles: col = wn*64 + jj*16 + ((lane>>4)<<3) + (lane&7); koff = ((lane>>3)&1)*4
    const int b_col = wn * 64 + ((lane >> 4) << 3) + (lane & 7);
    const int b_kw  = ((lane >> 3) & 1) * 4;

    float acc[4][8][4];
    #pragma unroll
    for (int i = 0; i < 4; i++)
        #pragma unroll
        for (int j = 0; j < 8; j++)
            #pragma unroll
            for (int q = 0; q < 4; q++) acc[i][j][q] = 0.f;

    const int nst = K / 32;

    GEMM_ISSUE(0, 0);
    GEMM_ISSUE(1, 1);
    asm volatile("cp.async.wait_group 1;\n");
    __syncthreads();

    for (int s = 0; s < nst; s++) {
        const int cur = s % 3;
        if (s + 2 < nst) GEMM_ISSUE(s + 2, (s + 2) % 3);

        const uint32_t stw = smem_base + (uint32_t)cur * (STAGE_W * 4);

        #pragma unroll
        for (int k0 = 0; k0 < 2; k0++) {
            const int kw = k0 * 8;
            uint32_t ah[4][4], al[4][4], bh[4][4], bl[4][4];
            #pragma unroll
            for (int i = 0; i < 4; i++) {
                const uint32_t off = (uint32_t)((a_row + i * 16) * GSTRIDE + kw + a_kw) * 4u;
                LDSM_X4(ah[i], stw + W_AH * 4u + off);
                LDSM_X4(al[i], stw + W_AL * 4u + off);
            }
            #pragma unroll
            for (int jj = 0; jj < 4; jj++) {
                const uint32_t off = (uint32_t)((b_col + jj * 16) * GSTRIDE + kw + b_kw) * 4u;
                LDSM_X4(bh[jj], stw + W_BH * 4u + off);
                LDSM_X4(bl[jj], stw + W_BL * 4u + off);
            }
            #pragma unroll
            for (int i = 0; i < 4; i++)
                #pragma unroll
                for (int j = 0; j < 8; j++) {
                    const int jj = j >> 1, o = (j & 1) * 2;
                    MMA_BF16(acc[i][j], ah[i][0], ah[i][1], ah[i][2], ah[i][3],
                             bh[jj][o], bh[jj][o + 1]);
                    MMA_BF16(acc[i][j], ah[i][0], ah[i][1], ah[i][2], ah[i][3],
                             bl[jj][o], bl[jj][o + 1]);
                    MMA_BF16(acc[i][j], al[i][0], al[i][1], al[i][2], al[i][3],
                             bh[jj][o], bh[jj][o + 1]);
                }
        }

        if (s + 1 < nst) {
            if (s + 2 < nst) asm volatile("cp.async.wait_group 1;\n");
            else             asm volatile("cp.async.wait_group 0;\n");
            __syncthreads();
        }
    }

    // epilogue
    #pragma unroll
    for (int j = 0; j < 8; j++) {
        const int col = bx * 256 + wn * 64 + j * 8 + 2 * c;
        float2 bv = make_float2(0.f, 0.f);
        if (bias) bv = *(const float2*)(bias + col);
        #pragma unroll
        for (int i = 0; i < 4; i++) {
            const int m1 = by * 128 + wm * 64 + i * 16 + r;
            const int m2 = m1 + 8;
            float2 o0 = make_float2(acc[i][j][0] + bv.x, acc[i][j][1] + bv.y);
            float2 o1 = make_float2(acc[i][j][2] + bv.x, acc[i][j][3] + bv.y);
            size_t p0 = (size_t)m1 * N + col;
            size_t p1 = (size_t)m2 * N + col;
            if (resid) {
                float2 r0 = *(const float2*)(resid + p0);
                float2 r1 = *(const float2*)(resid + p1);
                o0.x += r0.x; o0.y += r0.y;
                o1.x += r1.x; o1.y += r1.y;
            }
            *(float2*)(C + p0) = o0;
            *(float2*)(C + p1) = o1;
        }
    }
}

// ---------------------------------------------------------------------------
// RMSNorm + split fused
// ---------------------------------------------------------------------------
__global__ __launch_bounds__(256) void rmsnorm_split_kernel(
    const float* __restrict__ x, const float* __restrict__ w,
    __nv_bfloat16* __restrict__ hi, __nv_bfloat16* __restrict__ lo)
{
    const int row = blockIdx.x;
    const float4* xr = (const float4*)(x + (size_t)row * HDIM);
    float ss = 0.f;
    for (int i = threadIdx.x; i < HDIM / 4; i += 256) {
        float4 v = xr[i];
        ss += v.x * v.x + v.y * v.y + v.z * v.z + v.w * v.w;
    }
    #pragma unroll
    for (int o = 16; o > 0; o >>= 1) ss += __shfl_xor_sync(0xffffffffu, ss, o);
    __shared__ float red[8];
    __shared__ float s_scale;
    if ((threadIdx.x & 31) == 0) red[threadIdx.x >> 5] = ss;
    __syncthreads();
    if (threadIdx.x == 0) {
        float tot = 0.f;
        #pragma unroll
        for (int i = 0; i < 8; i++) tot += red[i];
        s_scale = rsqrtf(tot / (float)HDIM + 1e-6f);
    }
    __syncthreads();
    const float sc = s_scale;
    const float4* wr = (const float4*)w;
    uint32_t* hw = (uint32_t*)(hi + (size_t)row * HDIM);
    uint32_t* lw = (uint32_t*)(lo + (size_t)row * HDIM);
    for (int i = threadIdx.x; i < HDIM / 4; i += 256) {
        float4 v = xr[i], ww = wr[i];
        float y0 = v.x * sc * ww.x, y1 = v.y * sc * ww.y;
        float y2 = v.z * sc * ww.z, y3 = v.w * sc * ww.w;
        float l0, l1, l2, l3;
        hw[2 * i]     = pack_hi(y0, y1, &l0, &l1);
        hw[2 * i + 1] = pack_hi(y2, y3, &l2, &l3);
        lw[2 * i]     = pack_bf(l0, l1);
        lw[2 * i + 1] = pack_bf(l2, l3);
    }
}

// ---------------------------------------------------------------------------
// RoPE + split fused (position == row index)
// ---------------------------------------------------------------------------
__global__ void rope_split_kernel(const float* __restrict__ src,
                                  __nv_bfloat16* __restrict__ hi,
                                  __nv_bfloat16* __restrict__ lo)
{
    const int s = blockIdx.x;
    const int hh = blockIdx.y;
    const int d = threadIdx.x;  // 0..63
    const size_t o = (size_t)s * gridDim.y * DHEAD + hh * DHEAD;
    const double p = (double)s;
    const double invf = exp(-(double)d * 0.14391156831212787);
    const double ph = p * invf;
    const float cc = (float)cos(ph);
    const float si = (float)sin(ph);
    const float x1 = src[o + d];
    const float x2 = src[o + d + 64];
    const float y1 = x1 * cc - x2 * si;
    const float y2 = x2 * cc + x1 * si;
    __nv_bfloat16 h1 = __float2bfloat16_rn(y1);
    __nv_bfloat16 h2 = __float2bfloat16_rn(y2);
    hi[o + d]      = h1;
    hi[o + d + 64] = h2;
    lo[o + d]      = __float2bfloat16_rn(y1 - __bfloat162float(h1));
    lo[o + d + 64] = __float2bfloat16_rn(y2 - __bfloat162float(h2));
}

// ---------------------------------------------------------------------------
// Tensor-core flash attention (split-bf16, 3-term), causal. (R6-proven)
// ---------------------------------------------------------------------------
#define QSTR 68
#define PSTR 36
#define FL_QH 0
#define FL_QL (FL_QH + 64 * QSTR)
#define FL_KH (FL_QL + 64 * QSTR)
#define FL_KL (FL_KH + 64 * QSTR)
#define FL_VH (FL_KL + 64 * QSTR)
#define FL_VL (FL_VH + 64 * QSTR)
#define FL_PH (FL_VL + 64 * QSTR)
#define FL_PL (FL_PH + 64 * PSTR)
#define FL_SB (FL_PL + 64 * PSTR)
#define FL_RM (FL_SB + 64 * 66)
#define FL_RL (FL_RM + 64)
#define FL_RA (FL_RL + 64)
#define FL_WORDS (FL_RA + 64)
#define FL_SMEM_BYTES (FL_WORDS * 4)

__global__ __launch_bounds__(256) void flash_tc(
    const uint32_t* __restrict__ qh, const uint32_t* __restrict__ ql,
    const uint32_t* __restrict__ kh, const uint32_t* __restrict__ kl,
    const uint32_t* __restrict__ vh, const uint32_t* __restrict__ vl,
    __nv_bfloat16* __restrict__ ahi, __nv_bfloat16* __restrict__ alo)
{
    extern __shared__ uint32_t sw[];
    float* smf = (float*)sw;

    const int tid = threadIdx.x, warp = tid >> 5, lane = tid & 31;
    const int wm = warp >> 2, wn = warp & 3;
    const int r = lane >> 2, c = lane & 3;
    const int h = blockIdx.y, m0 = blockIdx.x * 64, kvh = h >> 2;
    const uint32_t smem_b = smem_u32(sw);
    const float scale = 0.08838834764831845f;

    for (int i = tid; i < 64 * 64; i += 256) {
        const int row = i >> 6, w = i & 63;
        const size_t g = (size_t)(m0 + row) * 2048 + h * 64 + w;
        sw[FL_QH + row * QSTR + w] = qh[g];
        sw[FL_QL + row * QSTR + w] = ql[g];
    }
    if (tid < 64) { smf[FL_RM + tid] = -INFINITY; smf[FL_RL + tid] = 0.f; }

    float accO[2][4][4];
    #pragma unroll
    for (int i = 0; i < 2; i++)
        #pragma unroll
        for (int j = 0; j < 4; j++)
            #pragma unroll
            for (int q = 0; q < 4; q++) accO[i][j][q] = 0.f;

    const int ntiles = blockIdx.x + 1;
    for (int t = 0; t < ntiles; ++t) {
        const int n0 = t * 64;
        __syncthreads();
        for (int i = tid; i < 64 * 64; i += 256) {
            const int row = i >> 6, w = i & 63;
            const size_t g = (size_t)(n0 + row) * 512 + kvh * 64 + w;
            sw[FL_KH + row * QSTR + w] = kh[g];
            sw[FL_KL + row * QSTR + w] = kl[g];
            sw[FL_VH + row * QSTR + w] = vh[g];
            sw[FL_VL + row * QSTR + w] = vl[g];
        }
        __syncthreads();

        float accS[2][2][4];
        #pragma unroll
        for (int i = 0; i < 2; i++)
            #pragma unroll
            for (int j = 0; j < 2; j++)
                #pragma unroll
                for (int q = 0; q < 4; q++) accS[i][j][q] = 0.f;

        #pragma unroll
        for (int ks = 0; ks < 8; ks++) {
            const int kw = ks * 8;
            uint32_t qa[2][4], qb[2][4];
            #pragma unroll
            for (int i = 0; i < 2; i++) {
                const int m = wm * 32 + i * 16 + r;
                const int o1 = m * QSTR + kw + c;
                const int o2 = (m + 8) * QSTR + kw + c;
                qa[i][0] = sw[FL_QH + o1];     qa[i][1] = sw[FL_QH + o2];
                qa[i][2] = sw[FL_QH + o1 + 4]; qa[i][3] = sw[FL_QH + o2 + 4];
                qb[i][0] = sw[FL_QL + o1];     qb[i][1] = sw[FL_QL + o2];
                qb[i][2] = sw[FL_QL + o1 + 4]; qb[i][3] = sw[FL_QL + o2 + 4];
            }
            #pragma unroll
            for (int j = 0; j < 2; j++) {
                const int n = wn * 16 + j * 8 + r;
                const int ob = n * QSTR + kw + c;
                const uint32_t kh0 = sw[FL_KH + ob], kh1 = sw[FL_KH + ob + 4];
                const uint32_t kl0 = sw[FL_KL + ob], kl1 = sw[FL_KL + ob + 4];
                #pragma unroll
                for (int i = 0; i < 2; i++) {
                    MMA_BF16(accS[i][j], qa[i][0], qa[i][1], qa[i][2], qa[i][3], kh0, kh1);
                    MMA_BF16(accS[i][j], qa[i][0], qa[i][1], qa[i][2], qa[i][3], kl0, kl1);
                    MMA_BF16(accS[i][j], qb[i][0], qb[i][1], qb[i][2], qb[i][3], kh0, kh1);
                }
            }
        }

        #pragma unroll
        for (int i = 0; i < 2; i++) {
            const int row0 = wm * 32 + i * 16 + r;
            #pragma unroll
            for (int j = 0; j < 2; j++) {
                const int col0 = wn * 16 + j * 8 + 2 * c;
                float v0 = accS[i][j][0] * scale;
                float v1 = accS[i][j][1] * scale;
                float v2 = accS[i][j][2] * scale;
                float v3 = accS[i][j][3] * scale;
                if (n0 + col0     > m0 + row0)     v0 = -1e30f;
                if (n0 + col0 + 1 > m0 + row0)     v1 = -1e30f;
                if (n0 + col0     > m0 + row0 + 8) v2 = -1e30f;
                if (n0 + col0 + 1 > m0 + row0 + 8) v3 = -1e30f;
                smf[FL_SB + row0 * 66 + col0]           = v0;
                smf[FL_SB + row0 * 66 + col0 + 1]       = v1;
                smf[FL_SB + (row0 + 8) * 66 + col0]     = v2;
                smf[FL_SB + (row0 + 8) * 66 + col0 + 1] = v3;
            }
        }
        __syncthreads();

        if (tid < 64) {
            float* pr = smf + FL_SB + tid * 66;
            float mloc = -INFINITY;
            #pragma unroll 8
            for (int cc = 0; cc < 64; ++cc) mloc = fmaxf(mloc, pr[cc]);
            const float mold = smf[FL_RM + tid];
            const float mnew = fmaxf(mold, mloc);
            const float alpha = (mold == -INFINITY) ? 0.f : expf(mold - mnew);
            float lsum = 0.f;
            #pragma unroll 8
            for (int cw = 0; cw < 32; ++cw) {
                const float p0 = expf(pr[2 * cw]     - mnew);
                const float p1 = expf(pr[2 * cw + 1] - mnew);
                lsum += p0 + p1;
                float l0, l1;
                sw[FL_PH + tid * PSTR + cw] = pack_hi(p0, p1, &l0, &l1);
                sw[FL_PL + tid * PSTR + cw] = pack_bf(l0, l1);
            }
            smf[FL_RL + tid] = smf[FL_RL + tid] * alpha + lsum;
            smf[FL_RM + tid] = mnew;
            smf[FL_RA + tid] = alpha;
        }
        __syncthreads();

        float al0[2], al1[2];
        #pragma unroll
        for (int i = 0; i < 2; i++) {
            al0[i] = smf[FL_RA + wm * 32 + i * 16 + r];
            al1[i] = smf[FL_RA + wm * 32 + i * 16 + r + 8];
        }
        #pragma unroll
        for (int i = 0; i < 2; i++)
            #pragma unroll
            for (int j = 0; j < 4; j++) {
                accO[i][j][0] *= al0[i]; accO[i][j][1] *= al0[i];
                accO[i][j][2] *= al1[i]; accO[i][j][3] *= al1[i];
            }

        #pragma unroll
        for (int ks = 0; ks < 4; ks++) {
            const int kw = ks * 8;
            uint32_t pa[2][4], pb[2][4];
            #pragma unroll
            for (int i = 0; i < 2; i++) {
                const int m = wm * 32 + i * 16 + r;
                const int o1 = m * PSTR + kw + c;
                const int o2 = (m + 8) * PSTR + kw + c;
                pa[i][0] = sw[FL_PH + o1];     pa[i][1] = sw[FL_PH + o2];
                pa[i][2] = sw[FL_PH + o1 + 4]; pa[i][3] = sw[FL_PH + o2 + 4];
                pb[i][0] = sw[FL_PL + o1];     pb[i][1] = sw[FL_PL + o2];
                pb[i][2] = sw[FL_PL + o1 + 4]; pb[i][3] = sw[FL_PL + o2 + 4];
            }
            #pragma unroll
            for (int j = 0; j < 4; j++) {
                const int jcol = wn * 32 + j * 8;
                const uint32_t addr_h = smem_b +
                    (uint32_t)(FL_VH + (ks * 16 + (lane & 15)) * QSTR + (jcol >> 1)) * 4u;
                const uint32_t addr_l = smem_b +
                    (uint32_t)(FL_VL + (ks * 16 + (lane & 15)) * QSTR + (jcol >> 1)) * 4u;
                uint32_t vh0, vh1, vl0, vl1;
                asm volatile("ldmatrix.sync.aligned.m8n8.x2.trans.shared.b16 {%0,%1},[%2];"
                             : "=r"(vh0), "=r"(vh1) : "r"(addr_h));
                asm volatile("ldmatrix.sync.aligned.m8n8.x2.trans.shared.b16 {%0,%1},[%2];"
                             : "=r"(vl0), "=r"(vl1) : "r"(addr_l));
                #pragma unroll
                for (int i = 0; i < 2; i++) {
                    MMA_BF16(accO[i][j], pa[i][0], pa[i][1], pa[i][2], pa[i][3], vh0, vh1);
                    MMA_BF16(accO[i][j], pa[i][0], pa[i][1], pa[i][2], pa[i][3], vl0, vl1);
                    MMA_BF16(accO[i][j], pb[i][0], pb[i][1], pb[i][2], pb[i][3], vh0, vh1);
                }
            }
        }
    }

    __syncthreads();
    #pragma unroll
    for (int i = 0; i < 2; i++) {
        const int row0 = wm * 32 + i * 16 + r;
        const float inv0 = 1.f / smf[FL_RL + row0];
        const float inv1 = 1.f / smf[FL_RL + row0 + 8];
        #pragma unroll
        for (int j = 0; j < 4; j++) {
            const int col = wn * 32 + j * 8 + 2 * c;
            const float x0 = accO[i][j][0] * inv0, x1 = accO[i][j][1] * inv0;
            const float x2 = accO[i][j][2] * inv1, x3 = accO[i][j][3] * inv1;
            const size_t g0 = (size_t)(m0 + row0) * 4096 + h * 128 + col;
            const size_t g1 = (size_t)(m0 + row0 + 8) * 4096 + h * 128 + col;
            float l0, l1, l2, l3;
            *(uint32_t*)(ahi + g0) = pack_hi(x0, x1, &l0, &l1);
            *(uint32_t*)(ahi + g1) = pack_hi(x2, x3, &l2, &l3);
            *(uint32_t*)(alo + g0) = pack_bf(l0, l1);
            *(uint32_t*)(alo + g1) = pack_bf(l2, l3);
        }
    }
}

// ---------------------------------------------------------------------------
// silu(gate)*up + split fused
// ---------------------------------------------------------------------------
__global__ void silu_mul_split_kernel(const float* __restrict__ g,
                                      const float* __restrict__ u,
                                      __nv_bfloat16* __restrict__ hi,
                                      __nv_bfloat16* __restrict__ lo, int n4)
{
    int i = blockIdx.x * blockDim.x + threadIdx.x;
    if (i >= n4) return;
    float4 gg = ((const float4*)g)[i];
    float4 uu = ((const float4*)u)[i];
    float y0 = gg.x / (1.f + expf(-gg.x)) * uu.x;
    float y1 = gg.y / (1.f + expf(-gg.y)) * uu.y;
    float y2 = gg.z / (1.f + expf(-gg.z)) * uu.z;
    float y3 = gg.w / (1.f + expf(-gg.w)) * uu.w;
    float l0, l1, l2, l3;
    ((uint32_t*)hi)[2 * i]     = pack_hi(y0, y1, &l0, &l1);
    ((uint32_t*)hi)[2 * i + 1] = pack_hi(y2, y3, &l2, &l3);
    ((uint32_t*)lo)[2 * i]     = pack_bf(l0, l1);
    ((uint32_t*)lo)[2 * i + 1] = pack_bf(l2, l3);
}

// ---------------------------------------------------------------------------
// Host orchestration
// ---------------------------------------------------------------------------
static inline void split_arr(const float* x, __nv_bfloat16* base, int n)
{
    split_kernel<<<(n / 4 + 255) / 256, 256>>>(x, base, base + n, n / 4);
}

static inline void gemm3(int M, int N, int K,
                         const __nv_bfloat16* Ab, int Aelems,
                         const __nv_bfloat16* Bb, int Belems,
                         const float* bias, const float* resid, float* C)
{
    gemm_bf16split<<<dim3(N / 256, M / 128), 256, GEMM_SMEM_BYTES>>>(
        M, N, K, Ab, Ab + Aelems, Bb, Bb + Belems, bias, resid, C);
}

extern "C" void kernel_launch(void* const* d_in, const int* in_sizes, int n_in,
                              void* d_out, int out_size)
{
    const float* hidden      = (const float*)d_in[0];
    const float* embeds      = (const float*)d_in[1];
    // d_in[2] attention_mask: all ones -> pad mask zero
    const float* fc_w        = (const float*)d_in[3];
    const float* fc_b        = (const float*)d_in[4];
    const float* in_norm_w   = (const float*)d_in[5];
    const float* q_w         = (const float*)d_in[6];
    const float* k_w         = (const float*)d_in[7];
    const float* v_w         = (const float*)d_in[8];
    const float* o_w         = (const float*)d_in[9];
    const float* post_norm_w = (const float*)d_in[10];
    const float* gate_w      = (const float*)d_in[11];
    const float* up_w        = (const float*)d_in[12];
    const float* down_w      = (const float*)d_in[13];
    // d_in[14] position_ids == arange(S)

    float* pool = nullptr;
    cudaGetSymbolAddress((void**)&pool, g_pool);
    float* x    = pool + OFF_X;
    float* q    = pool + OFF_Q;
    float* k    = pool + OFF_K;
    float* v    = pool + OFF_V;
    float* x2   = pool + OFF_X2;
    float* gate = pool + OFF_GATE;
    float* up   = pool + OFF_UP;

    __nv_bfloat16* bp = nullptr;
    cudaGetSymbolAddress((void**)&bp, g_bpool);

    cudaFuncSetAttribute(flash_tc,
                         cudaFuncAttributeMaxDynamicSharedMemorySize, FL_SMEM_BYTES);
    cudaFuncSetAttribute(gemm_bf16split,
                         cudaFuncAttributeMaxDynamicSharedMemorySize, GEMM_SMEM_BYTES);

    // weight splits
    split_arr(fc_w,   bp + BO_FCW, BE_FCW);
    split_arr(q_w,    bp + BO_QW,  BE_QW);
    split_arr(k_w,    bp + BO_KW,  BE_KW);
    split_arr(v_w,    bp + BO_VW,  BE_KW);
    split_arr(o_w,    bp + BO_OW,  BE_OW);
    split_arr(gate_w, bp + BO_GW,  BE_GW);
    split_arr(up_w,   bp + BO_UW,  BE_GW);
    split_arr(down_w, bp + BO_DW,  BE_DW);

    // 1. concat+split
    {
        const int n4 = S_LEN * 2 * HDIM / 4;
        concat_split_kernel<<<(n4 + 255) / 256, 256>>>(
            embeds, hidden, bp + BO_CAT, bp + BO_CAT + BE_CAT);
    }
    // 2. fc
    gemm3(S_LEN, HDIM, 2 * HDIM, bp + BO_CAT, BE_CAT, bp + BO_FCW, BE_FCW,
          fc_b, nullptr, x);
    // 3. rmsnorm1 + split
    rmsnorm_split_kernel<<<S_LEN, 256>>>(x, in_norm_w,
                                         bp + BO_H, bp + BO_H + BE_H);
    // 4. qkv
    gemm3(S_LEN, NHEADS * DHEAD, HDIM, bp + BO_H, BE_H, bp + BO_QW, BE_QW,
          nullptr, nullptr, q);
    gemm3(S_LEN, NKVH * DHEAD, HDIM, bp + BO_H, BE_H, bp + BO_KW, BE_KW,
          nullptr, nullptr, k);
    gemm3(S_LEN, NKVH * DHEAD, HDIM, bp + BO_H, BE_H, bp + BO_VW, BE_KW,
          nullptr, nullptr, v);
    // 5. RoPE + split (q,k); plain split (v)
    rope_split_kernel<<<dim3(S_LEN, NHEADS), 64>>>(q, bp + BO_QB, bp + BO_QB + BE_ATTN);
    rope_split_kernel<<<dim3(S_LEN, NKVH),  64>>>(k, bp + BO_KB, bp + BO_KB + BE_KV);
    split_arr(v, bp + BO_VB, BE_KV);
    // 6. flash attention
    flash_tc<<<dim3(S_LEN / 64, NHEADS), 256, FL_SMEM_BYTES>>>(
        (const uint32_t*)(bp + BO_QB), (const uint32_t*)(bp + BO_QB + BE_ATTN),
        (const uint32_t*)(bp + BO_KB), (const uint32_t*)(bp + BO_KB + BE_KV),
        (const uint32_t*)(bp + BO_VB), (const uint32_t*)(bp + BO_VB + BE_KV),
        bp + BO_ATTN, bp + BO_ATTN + BE_ATTN);
    // 7. O proj + residual
    gemm3(S_LEN, HDIM, NHEADS * DHEAD, bp + BO_ATTN, BE_ATTN, bp + BO_OW, BE_OW,
          nullptr, x, x2);
    // 8. rmsnorm2 + split
    rmsnorm_split_kernel<<<S_LEN, 256>>>(x2, post_norm_w,
                                         bp + BO_H2, bp + BO_H2 + BE_H);
    // 9. gate / up
    gemm3(S_LEN, IDIM, HDIM, bp + BO_H2, BE_H, bp + BO_GW, BE_GW,
          nullptr, nullptr, gate);
    gemm3(S_LEN, IDIM, HDIM, bp + BO_H2, BE_H, bp + BO_UW, BE_GW,
          nullptr, nullptr, up);
    // 10. silu*up + split
    {
        const int n4 = S_LEN * IDIM / 4;
        silu_mul_split_kernel<<<(n4 + 255) / 256, 256>>>(
            gate, up, bp + BO_ACT, bp + BO_ACT + BE_ACT, n4);
    }
    // 11. down + residual -> out
    gemm3(S_LEN, HDIM, IDIM, bp + BO_ACT, BE_ACT, bp + BO_DW, BE_DW,
          nullptr, x2, (float*)d_out);
}